// round 5
// baseline (speedup 1.0000x reference)
#include <cuda_runtime.h>
#include <cuda_bf16.h>
#include <cstdint>

// Problem constants
#define N_ROWS 8192
#define HDIM   1024
#define B0DIM  64
#define FDIM   2048
#define ODIM   2048
#define XDIM   (HDIM + B0DIM + FDIM)   // 3136
#define NB     6

#define BM 128
#define BN 128
#define BK 32
#define SSTR 40   // bf16 elements per smem row (80B) -> conflict-free ldmatrix

// PRE (A-operand producer fusion):
// 0: a = A
// 1: a = A * P2                      (q * rS)
// 2: a = A * (P2 + P3)               (Aq * (q + sumq))
// 3: a = (A + P2 + P3) * P4          ((h + sumh + rqh) * Dh)

// -------------------- scratch (device globals; no allocs allowed) ---------
__device__ float g_q   [N_ROWS * FDIM];
__device__ float g_sumq[N_ROWS * FDIM];
__device__ float g_rS  [N_ROWS * FDIM];
__device__ float g_Aq  [N_ROWS * FDIM];
__device__ float g_sumh[N_ROWS * HDIM];
__device__ float g_rqh [N_ROWS * HDIM];
__device__ float g_Dh  [N_ROWS * HDIM];
__device__ float g_h   [N_ROWS * HDIM];

// -------------------- helpers ---------------------------------------------
__device__ __forceinline__ void ldsm_x4(uint32_t& r0, uint32_t& r1,
                                        uint32_t& r2, uint32_t& r3,
                                        uint32_t addr)
{
    asm volatile("ldmatrix.sync.aligned.m8n8.x4.shared.b16 {%0,%1,%2,%3}, [%4];"
                 : "=r"(r0), "=r"(r1), "=r"(r2), "=r"(r3) : "r"(addr));
}

__device__ __forceinline__ void mma16816(float* c, const uint32_t* a,
                                         uint32_t b0, uint32_t b1)
{
    asm volatile(
        "mma.sync.aligned.m16n8k16.row.col.f32.bf16.bf16.f32 "
        "{%0,%1,%2,%3}, {%4,%5,%6,%7}, {%8,%9}, {%0,%1,%2,%3};"
        : "+f"(c[0]), "+f"(c[1]), "+f"(c[2]), "+f"(c[3])
        : "r"(a[0]), "r"(a[1]), "r"(a[2]), "r"(a[3]), "r"(b0), "r"(b1));
}

__device__ __forceinline__ void cvt2(float x, float y, uint32_t& hi, uint32_t& lo)
{
    __nv_bfloat16 hx = __float2bfloat16(x);
    __nv_bfloat16 hy = __float2bfloat16(y);
    __nv_bfloat16 lx = __float2bfloat16(x - __bfloat162float(hx));
    __nv_bfloat16 ly = __float2bfloat16(y - __bfloat162float(hy));
    hi = (uint32_t(__bfloat16_as_ushort(hy)) << 16) | __bfloat16_as_ushort(hx);
    lo = (uint32_t(__bfloat16_as_ushort(ly)) << 16) | __bfloat16_as_ushort(lx);
}

__device__ __forceinline__ void cvt8(float4 a, float4 b, uint4& hi, uint4& lo)
{
    uint32_t h0, l0, h1, l1, h2, l2, h3, l3;
    cvt2(a.x, a.y, h0, l0);
    cvt2(a.z, a.w, h1, l1);
    cvt2(b.x, b.y, h2, l2);
    cvt2(b.z, b.w, h3, l3);
    hi = make_uint4(h0, h1, h2, h3);
    lo = make_uint4(l0, l1, l2, l3);
}

// combined A-operand loader (PRE fusion). For PRE>0, all tensors share lda==K.
template <int PRE>
__device__ __forceinline__ float4 ld4(const float* __restrict__ A,
                                      const float* __restrict__ P2,
                                      const float* __restrict__ P3,
                                      const float* __restrict__ P4,
                                      size_t idx)
{
    float4 a = *(const float4*)(A + idx);
    if (PRE == 1) {
        float4 b = *(const float4*)(P2 + idx);
        a.x *= b.x; a.y *= b.y; a.z *= b.z; a.w *= b.w;
    }
    if (PRE == 2) {
        float4 b = *(const float4*)(P2 + idx);
        float4 c = *(const float4*)(P3 + idx);
        a.x *= (b.x + c.x); a.y *= (b.y + c.y);
        a.z *= (b.z + c.z); a.w *= (b.w + c.w);
    }
    if (PRE == 3) {
        float4 b = *(const float4*)(P2 + idx);
        float4 c = *(const float4*)(P3 + idx);
        float4 d = *(const float4*)(P4 + idx);
        a.x = (a.x + b.x + c.x) * d.x; a.y = (a.y + b.y + c.y) * d.y;
        a.z = (a.z + b.z + c.z) * d.z; a.w = (a.w + b.w + c.w) * d.w;
    }
    return a;
}

// -------------------- bf16x3 tensor-core GEMM (v3) ------------------------
// C = epi(preA[M,K] @ W[Fout,K]^T + bias)
// MODE 0: C = acc + b ; 1: relu ; 2: C += acc + b ; 3: C = C - leaky(acc+b)
template <int MODE, int PRE>
__global__ __launch_bounds__(256, 2) void gemm_v3(
    const float* __restrict__ A, int lda,
    const float* __restrict__ W,          // [Fout, K] row-major
    const float* __restrict__ bias,
    float* __restrict__ C, int ldc,
    int K,
    const float* __restrict__ a_ptr,
    const float* __restrict__ P2,
    const float* __restrict__ P3,
    const float* __restrict__ P4)
{
    __shared__ __nv_bfloat16 sAhi[BM * SSTR];
    __shared__ __nv_bfloat16 sAlo[BM * SSTR];
    __shared__ __nv_bfloat16 sBhi[BN * SSTR];
    __shared__ __nv_bfloat16 sBlo[BN * SSTR];

    const int t    = threadIdx.x;
    const int lane = t & 31;
    const int warp = t >> 5;
    const int wm   = warp >> 1;      // 0..3
    const int wn   = warp & 1;       // 0..1
    const int m0   = wm * 32;        // warp tile 32x64
    const int n0   = wn * 64;
    const int brow = blockIdx.y * BM;
    const int bcol = blockIdx.x * BN;

    // load mapping: thread -> (row = t/2, k-half = (t&1)*16), 16 floats each
    const int lrow = t >> 1;
    const int lk   = (t & 1) * 16;
    const size_t aBase = (size_t)(brow + lrow) * lda + lk;
    const float* Wrow  = W + (size_t)(bcol + lrow) * K + lk;

    __nv_bfloat16* saHi = sAhi + lrow * SSTR + lk;
    __nv_bfloat16* saLo = sAlo + lrow * SSTR + lk;
    __nv_bfloat16* sbHi = sBhi + lrow * SSTR + lk;
    __nv_bfloat16* sbLo = sBlo + lrow * SSTR + lk;

    float acc[2][8][4];
#pragma unroll
    for (int mt = 0; mt < 2; mt++)
#pragma unroll
        for (int nt = 0; nt < 8; nt++)
#pragma unroll
            for (int i = 0; i < 4; i++) acc[mt][nt][i] = 0.f;

    const uint32_t baseAhi = (uint32_t)__cvta_generic_to_shared(sAhi);
    const uint32_t baseAlo = (uint32_t)__cvta_generic_to_shared(sAlo);
    const uint32_t baseBhi = (uint32_t)__cvta_generic_to_shared(sBhi);
    const uint32_t baseBlo = (uint32_t)__cvta_generic_to_shared(sBlo);

    const int aoffA = (m0 + (lane & 15)) * SSTR + ((lane >> 4) << 3);
    const int aoffB = (n0 + (lane & 7) + ((lane >> 4) << 3)) * SSTR + (((lane >> 3) & 1) << 3);

    const int nch = K / BK;

    // prefetch A chunk 0
    float4 ar[4];
#pragma unroll
    for (int g = 0; g < 4; g++)
        ar[g] = ld4<PRE>(A, P2, P3, P4, aBase + g * 4);

    for (int c = 0; c < nch; c++) {
        const int k0 = c * BK;
        // B loads for this chunk (latency overlapped by A's STS below)
        float4 br[4];
#pragma unroll
        for (int g = 0; g < 4; g++)
            br[g] = *(const float4*)(Wrow + k0 + g * 4);

        __syncthreads();   // previous MMA readers done
        {
            uint4 h0, l0, h1, l1;
            cvt8(ar[0], ar[1], h0, l0);
            cvt8(ar[2], ar[3], h1, l1);
            *(uint4*)(saHi + 0) = h0; *(uint4*)(saHi + 8) = h1;
            *(uint4*)(saLo + 0) = l0; *(uint4*)(saLo + 8) = l1;
            cvt8(br[0], br[1], h0, l0);
            cvt8(br[2], br[3], h1, l1);
            *(uint4*)(sbHi + 0) = h0; *(uint4*)(sbHi + 8) = h1;
            *(uint4*)(sbLo + 0) = l0; *(uint4*)(sbLo + 8) = l1;
        }
        __syncthreads();

        // prefetch next A chunk (LDG latency hidden under MMA section)
        if (c + 1 < nch) {
#pragma unroll
            for (int g = 0; g < 4; g++)
                ar[g] = ld4<PRE>(A, P2, P3, P4, aBase + (c + 1) * BK + g * 4);
        }

        // ---- MMA: per kk, fragment-reusing pass order hihi -> lo*Bhi -> Ahi*Blo
#pragma unroll
        for (int kk = 0; kk < BK; kk += 16) {
            uint32_t b[4][4];
#pragma unroll
            for (int g = 0; g < 4; g++)
                ldsm_x4(b[g][0], b[g][1], b[g][2], b[g][3],
                        baseBhi + (uint32_t)(aoffB + g * 16 * SSTR + kk) * 2u);
            uint32_t a[2][4];
#pragma unroll
            for (int mt = 0; mt < 2; mt++)
                ldsm_x4(a[mt][0], a[mt][1], a[mt][2], a[mt][3],
                        baseAhi + (uint32_t)(aoffA + mt * 16 * SSTR + kk) * 2u);
            // pass 1: Ahi * Bhi
#pragma unroll
            for (int mt = 0; mt < 2; mt++)
#pragma unroll
                for (int nt = 0; nt < 8; nt++)
                    mma16816(acc[mt][nt], a[mt],
                             b[nt >> 1][(nt & 1) * 2], b[nt >> 1][(nt & 1) * 2 + 1]);
            // pass 2: Alo * Bhi (Bhi reused)
            uint32_t a2[2][4];
#pragma unroll
            for (int mt = 0; mt < 2; mt++)
                ldsm_x4(a2[mt][0], a2[mt][1], a2[mt][2], a2[mt][3],
                        baseAlo + (uint32_t)(aoffA + mt * 16 * SSTR + kk) * 2u);
#pragma unroll
            for (int mt = 0; mt < 2; mt++)
#pragma unroll
                for (int nt = 0; nt < 8; nt++)
                    mma16816(acc[mt][nt], a2[mt],
                             b[nt >> 1][(nt & 1) * 2], b[nt >> 1][(nt & 1) * 2 + 1]);
            // pass 3: Ahi * Blo (Ahi reused, b regs overwritten)
#pragma unroll
            for (int g = 0; g < 4; g++)
                ldsm_x4(b[g][0], b[g][1], b[g][2], b[g][3],
                        baseBlo + (uint32_t)(aoffB + g * 16 * SSTR + kk) * 2u);
#pragma unroll
            for (int mt = 0; mt < 2; mt++)
#pragma unroll
                for (int nt = 0; nt < 8; nt++)
                    mma16816(acc[mt][nt], a[mt],
                             b[nt >> 1][(nt & 1) * 2], b[nt >> 1][(nt & 1) * 2 + 1]);
        }
    }

    // ---- epilogue ----
    const float alpha = (MODE == 3) ? a_ptr[0] : 0.f;
#pragma unroll
    for (int mt = 0; mt < 2; mt++) {
#pragma unroll
        for (int half = 0; half < 2; half++) {
            const int row = brow + m0 + mt * 16 + (lane >> 2) + half * 8;
            float* Crow = C + (size_t)row * ldc + bcol + n0 + (lane & 3) * 2;
            const float* brow_b = bias + bcol + n0 + (lane & 3) * 2;
#pragma unroll
            for (int nt = 0; nt < 8; nt++) {
                float v0 = acc[mt][nt][half * 2 + 0] + brow_b[nt * 8 + 0];
                float v1 = acc[mt][nt][half * 2 + 1] + brow_b[nt * 8 + 1];
                if (MODE == 1) {
                    v0 = v0 > 0.f ? v0 : 0.f;
                    v1 = v1 > 0.f ? v1 : 0.f;
                }
                if (MODE == 2) {
                    float2 old = *(float2*)(Crow + nt * 8);
                    v0 += old.x; v1 += old.y;
                }
                if (MODE == 3) {
                    float2 old = *(float2*)(Crow + nt * 8);
                    float l0 = (v0 >= 0.f) ? v0 : alpha * v0;
                    float l1 = (v1 >= 0.f) ? v1 : alpha * v1;
                    v0 = old.x - l0; v1 = old.y - l1;
                }
                *(float2*)(Crow + nt * 8) = make_float2(v0, v1);
            }
        }
    }
}

// -------------------- q = (pi/4) * d^2 ------------------------------------
__global__ __launch_bounds__(256) void k_square(const float* __restrict__ x,
                                                float* __restrict__ q)
{
    const int i = blockIdx.x * blockDim.x + threadIdx.x;
    const int row = i / (FDIM / 4);
    const int c4  = i % (FDIM / 4);
    const float4 d = *(const float4*)(x + (size_t)row * XDIM + HDIM + B0DIM + c4 * 4);
    const float s = 0.78539816339744830962f;
    float4 o;
    o.x = s * d.x * d.x; o.y = s * d.y * d.y;
    o.z = s * d.z * d.z; o.w = s * d.w * d.w;
    *(float4*)(q + (size_t)row * FDIM + c4 * 4) = o;
}

// -------------------- driver ----------------------------------------------
extern "C" void kernel_launch(void* const* d_in, const int* in_sizes, int n_in,
                              void* d_out, int out_size)
{
    const float* x      = (const float*)d_in[0];
    const float* W_h0q  = (const float*)d_in[1];
    const float* b_h0q  = (const float*)d_in[2];
    const float* W_sq   = (const float*)d_in[3];
    const float* b_sq   = (const float*)d_in[4];
    const float* W_h0h  = (const float*)d_in[5];
    const float* b_h0h  = (const float*)d_in[6];
    const float* W_S    = (const float*)d_in[7];
    const float* b_S    = (const float*)d_in[8];
    const float* W_q0h  = (const float*)d_in[9];
    const float* b_q0h  = (const float*)d_in[10];
    const float* Wb_Aq  = (const float*)d_in[11];
    const float* bb_Aq  = (const float*)d_in[12];
    const float* Wb_Dh  = (const float*)d_in[13];
    const float* bb_Dh  = (const float*)d_in[14];
    const float* Wb_fh  = (const float*)d_in[15];
    const float* bb_fh  = (const float*)d_in[16];
    const float* Wb_hf  = (const float*)d_in[17];
    const float* bb_hf  = (const float*)d_in[18];
    const float* a_hf   = (const float*)d_in[19];
    const float* Wb_resq= (const float*)d_in[20];
    const float* bb_resq= (const float*)d_in[21];
    const float* W_out  = (const float*)d_in[22];
    const float* b_out  = (const float*)d_in[23];

    float *q, *sumq, *rS, *Aq, *sumh, *rqh, *Dh, *hb;
    cudaGetSymbolAddress((void**)&q,    g_q);
    cudaGetSymbolAddress((void**)&sumq, g_sumq);
    cudaGetSymbolAddress((void**)&rS,   g_rS);
    cudaGetSymbolAddress((void**)&Aq,   g_Aq);
    cudaGetSymbolAddress((void**)&sumh, g_sumh);
    cudaGetSymbolAddress((void**)&rqh,  g_rqh);
    cudaGetSymbolAddress((void**)&Dh,   g_Dh);
    cudaGetSymbolAddress((void**)&hb,   g_h);

    const dim3 gF(FDIM / BN, N_ROWS / BM);   // (16, 64)
    const dim3 gH(HDIM / BN, N_ROWS / BM);   // (8, 64)
    const int ewF = (N_ROWS * FDIM / 4) / 256;

    // ---- prologue ----
    gemm_v3<0, 0><<<gF, 256>>>(x + HDIM, XDIM, W_h0q, b_h0q, sumq, FDIM, B0DIM,
                               nullptr, nullptr, nullptr, nullptr);
    gemm_v3<2, 0><<<gF, 256>>>(x, XDIM, W_sq, b_sq, sumq, FDIM, HDIM,
                               nullptr, nullptr, nullptr, nullptr);
    gemm_v3<0, 0><<<gH, 256>>>(x + HDIM, XDIM, W_h0h, b_h0h, sumh, HDIM, B0DIM,
                               nullptr, nullptr, nullptr, nullptr);
    gemm_v3<1, 0><<<gF, 256>>>(x + HDIM + B0DIM, XDIM, W_S, b_S, rS, FDIM, FDIM,
                               nullptr, nullptr, nullptr, nullptr);
    k_square<<<ewF, 256>>>(x, q);
    gemm_v3<0, 0><<<gH, 256>>>(q, FDIM, W_q0h, b_q0h, rqh, HDIM, FDIM,
                               nullptr, nullptr, nullptr, nullptr);

    // ---- 6 unrolled blocks ----
    for (int nb = 0; nb < NB; nb++) {
        const float* wAq   = Wb_Aq   + (size_t)nb * FDIM * FDIM;
        const float* bAq   = bb_Aq   + (size_t)nb * FDIM;
        const float* wDh   = Wb_Dh   + (size_t)nb * HDIM * FDIM;
        const float* bDh   = bb_Dh   + (size_t)nb * HDIM;
        const float* wfh   = Wb_fh   + (size_t)nb * HDIM * FDIM;
        const float* bfh   = bb_fh   + (size_t)nb * HDIM;
        const float* whf   = Wb_hf   + (size_t)nb * FDIM * HDIM;
        const float* bhf   = bb_hf   + (size_t)nb * FDIM;
        const float* wresq = Wb_resq + (size_t)nb * HDIM * FDIM;
        const float* bresq = bb_resq + (size_t)nb * HDIM;

        // A_q = (q * rS) @ W_Aq^T + b        (PRE_MUL fused)
        gemm_v3<0, 1><<<gF, 256>>>(q, FDIM, wAq, bAq, Aq, FDIM, FDIM,
                                   nullptr, rS, nullptr, nullptr);
        // D_h = relu(A_q @ W_Dh^T + b)
        gemm_v3<1, 0><<<gH, 256>>>(Aq, FDIM, wDh, bDh, Dh, HDIM, FDIM,
                                   nullptr, nullptr, nullptr, nullptr);
        // h = relu((A_q * (q + sumq)) @ W_fh^T + b)   (PRE_HID fused)
        gemm_v3<1, 2><<<gH, 256>>>(Aq, FDIM, wfh, bfh, hb, HDIM, FDIM,
                                   nullptr, q, sumq, nullptr);
        // q = q - leaky(((h + sumh + rqh) * D_h) @ W_hf^T + b)   (PRE_COMB fused)
        gemm_v3<3, 3><<<gF, 256>>>(hb, HDIM, whf, bhf, q, FDIM, HDIM,
                                   a_hf + nb, sumh, rqh, Dh);
        // res_q_h = relu(q @ W_resq^T + b)
        gemm_v3<1, 0><<<gH, 256>>>(q, FDIM, wresq, bresq, rqh, HDIM, FDIM,
                                   nullptr, nullptr, nullptr, nullptr);
    }

    // ---- output ----
    gemm_v3<0, 0><<<gF, 256>>>(q, FDIM, W_out, b_out, (float*)d_out, ODIM, FDIM,
                               nullptr, nullptr, nullptr, nullptr);
}

// round 6
// speedup vs baseline: 1.0532x; 1.0532x over previous
#include <cuda_runtime.h>
#include <cuda_bf16.h>
#include <cstdint>

// Problem constants
#define N_ROWS 8192
#define HDIM   1024
#define B0DIM  64
#define FDIM   2048
#define ODIM   2048
#define XDIM   (HDIM + B0DIM + FDIM)   // 3136
#define NB     6

#define BM 128
#define BN 128
#define BK 32
#define SSTR 40   // bf16 elements per smem row (80B) -> conflict-free ldmatrix

// double-buffered smem stage layout (bytes)
#define OFF_AHI  0
#define OFF_ALO  10240
#define OFF_BHI  20480
#define OFF_BLO  30720
#define SM_STAGE 40960
#define SMEM_TOTAL (2 * SM_STAGE)   // 81920

// -------------------- scratch (device globals; no allocs allowed) ---------
__device__ float g_q   [N_ROWS * FDIM];
__device__ float g_sumq[N_ROWS * FDIM];
__device__ float g_rS  [N_ROWS * FDIM];
__device__ float g_t   [N_ROWS * FDIM];
__device__ float g_Aq  [N_ROWS * FDIM];
__device__ float g_sumh[N_ROWS * HDIM];
__device__ float g_rqh [N_ROWS * HDIM];
__device__ float g_Dh  [N_ROWS * HDIM];
__device__ float g_h   [N_ROWS * HDIM];
__device__ float g_th  [N_ROWS * HDIM];

// -------------------- helpers ---------------------------------------------
__device__ __forceinline__ void ldsm_x4(uint32_t& r0, uint32_t& r1,
                                        uint32_t& r2, uint32_t& r3,
                                        uint32_t addr)
{
    asm volatile("ldmatrix.sync.aligned.m8n8.x4.shared.b16 {%0,%1,%2,%3}, [%4];"
                 : "=r"(r0), "=r"(r1), "=r"(r2), "=r"(r3) : "r"(addr));
}

__device__ __forceinline__ void mma16816(float* c, const uint32_t* a,
                                         uint32_t b0, uint32_t b1)
{
    asm volatile(
        "mma.sync.aligned.m16n8k16.row.col.f32.bf16.bf16.f32 "
        "{%0,%1,%2,%3}, {%4,%5,%6,%7}, {%8,%9}, {%0,%1,%2,%3};"
        : "+f"(c[0]), "+f"(c[1]), "+f"(c[2]), "+f"(c[3])
        : "r"(a[0]), "r"(a[1]), "r"(a[2]), "r"(a[3]), "r"(b0), "r"(b1));
}

__device__ __forceinline__ void cvt2(float x, float y, uint32_t& hi, uint32_t& lo)
{
    __nv_bfloat16 hx = __float2bfloat16(x);
    __nv_bfloat16 hy = __float2bfloat16(y);
    __nv_bfloat16 lx = __float2bfloat16(x - __bfloat162float(hx));
    __nv_bfloat16 ly = __float2bfloat16(y - __bfloat162float(hy));
    hi = (uint32_t(__bfloat16_as_ushort(hy)) << 16) | __bfloat16_as_ushort(hx);
    lo = (uint32_t(__bfloat16_as_ushort(ly)) << 16) | __bfloat16_as_ushort(lx);
}

__device__ __forceinline__ void cvt8(float4 a, float4 b, uint4& hi, uint4& lo)
{
    uint32_t h0, l0, h1, l1, h2, l2, h3, l3;
    cvt2(a.x, a.y, h0, l0);
    cvt2(a.z, a.w, h1, l1);
    cvt2(b.x, b.y, h2, l2);
    cvt2(b.z, b.w, h3, l3);
    hi = make_uint4(h0, h1, h2, h3);
    lo = make_uint4(l0, l1, l2, l3);
}

// -------------------- double-buffered bf16x3 tensor GEMM ------------------
// C = epi(A[M,K] @ W[Fout,K]^T + bias)
// MODE 0: C = acc + b ; 1: relu ; 2: C += acc + b ; 3: C = C - leaky(acc+b)
template <int MODE>
__global__ __launch_bounds__(256, 2) void gemm_db(
    const float* __restrict__ A, int lda,
    const float* __restrict__ W,          // [Fout, K] row-major
    const float* __restrict__ bias,
    float* __restrict__ C, int ldc,
    int K,
    const float* __restrict__ a_ptr)
{
    extern __shared__ __align__(16) char smem[];
    const uint32_t sb = (uint32_t)__cvta_generic_to_shared(smem);

    const int t    = threadIdx.x;
    const int lane = t & 31;
    const int warp = t >> 5;
    const int wm   = warp >> 1;      // 0..3
    const int wn   = warp & 1;       // 0..1
    const int m0   = wm * 32;        // warp tile 32x64
    const int n0   = wn * 64;
    const int brow = blockIdx.y * BM;
    const int bcol = blockIdx.x * BN;

    // load mapping: thread -> (row = t/2, k-half = (t&1)*16), 16 floats each
    const int lrow = t >> 1;
    const int lk   = (t & 1) * 16;
    const float* Ap = A + (size_t)(brow + lrow) * lda + lk;
    const float* Wp = W + (size_t)(bcol + lrow) * K   + lk;
    const int eoff = (lrow * SSTR + lk) * 2;   // byte offset within each array

    float acc[2][8][4];
#pragma unroll
    for (int mt = 0; mt < 2; mt++)
#pragma unroll
        for (int nt = 0; nt < 8; nt++)
#pragma unroll
            for (int i = 0; i < 4; i++) acc[mt][nt][i] = 0.f;

    const int aoffA = ((m0 + (lane & 15)) * SSTR + ((lane >> 4) << 3)) * 2;
    const int aoffB = ((n0 + (lane & 7) + ((lane >> 4) << 3)) * SSTR
                       + (((lane >> 3) & 1) << 3)) * 2;

    const int nch = K / BK;

    float4 av[4], wv[4];
#pragma unroll
    for (int g = 0; g < 4; g++) {
        av[g] = *(const float4*)(Ap + g * 4);
        wv[g] = *(const float4*)(Wp + g * 4);
    }
    // store chunk 0 into stage 0
    {
        char* stg = smem;
        uint4 h0, l0, h1, l1;
        cvt8(av[0], av[1], h0, l0);
        cvt8(av[2], av[3], h1, l1);
        *(uint4*)(stg + OFF_AHI + eoff)      = h0;
        *(uint4*)(stg + OFF_AHI + eoff + 16) = h1;
        *(uint4*)(stg + OFF_ALO + eoff)      = l0;
        *(uint4*)(stg + OFF_ALO + eoff + 16) = l1;
        cvt8(wv[0], wv[1], h0, l0);
        cvt8(wv[2], wv[3], h1, l1);
        *(uint4*)(stg + OFF_BHI + eoff)      = h0;
        *(uint4*)(stg + OFF_BHI + eoff + 16) = h1;
        *(uint4*)(stg + OFF_BLO + eoff)      = l0;
        *(uint4*)(stg + OFF_BLO + eoff + 16) = l1;
    }
    __syncthreads();

    for (int c = 0; c < nch; c++) {
        // prefetch chunk c+1 (hidden under MMA below)
        if (c + 1 < nch) {
            const int k1 = (c + 1) * BK;
#pragma unroll
            for (int g = 0; g < 4; g++) {
                av[g] = *(const float4*)(Ap + k1 + g * 4);
                wv[g] = *(const float4*)(Wp + k1 + g * 4);
            }
        }

        // ---- MMA from stage c&1; reuse-order passes: hihi -> Alo*Bhi -> Ahi*Blo
        const uint32_t stgb = sb + (uint32_t)(c & 1) * SM_STAGE;
#pragma unroll
        for (int kk = 0; kk < BK; kk += 16) {
            uint32_t b[4][4];
#pragma unroll
            for (int g = 0; g < 4; g++)
                ldsm_x4(b[g][0], b[g][1], b[g][2], b[g][3],
                        stgb + OFF_BHI + (uint32_t)(aoffB + (g * 16 * SSTR + kk) * 2));
            uint32_t a[2][4];
#pragma unroll
            for (int mt = 0; mt < 2; mt++)
                ldsm_x4(a[mt][0], a[mt][1], a[mt][2], a[mt][3],
                        stgb + OFF_AHI + (uint32_t)(aoffA + (mt * 16 * SSTR + kk) * 2));
#pragma unroll
            for (int mt = 0; mt < 2; mt++)
#pragma unroll
                for (int nt = 0; nt < 8; nt++)
                    mma16816(acc[mt][nt], a[mt],
                             b[nt >> 1][(nt & 1) * 2], b[nt >> 1][(nt & 1) * 2 + 1]);
            uint32_t a2[2][4];
#pragma unroll
            for (int mt = 0; mt < 2; mt++)
                ldsm_x4(a2[mt][0], a2[mt][1], a2[mt][2], a2[mt][3],
                        stgb + OFF_ALO + (uint32_t)(aoffA + (mt * 16 * SSTR + kk) * 2));
#pragma unroll
            for (int mt = 0; mt < 2; mt++)
#pragma unroll
                for (int nt = 0; nt < 8; nt++)
                    mma16816(acc[mt][nt], a2[mt],
                             b[nt >> 1][(nt & 1) * 2], b[nt >> 1][(nt & 1) * 2 + 1]);
#pragma unroll
            for (int g = 0; g < 4; g++)
                ldsm_x4(b[g][0], b[g][1], b[g][2], b[g][3],
                        stgb + OFF_BLO + (uint32_t)(aoffB + (g * 16 * SSTR + kk) * 2));
#pragma unroll
            for (int mt = 0; mt < 2; mt++)
#pragma unroll
                for (int nt = 0; nt < 8; nt++)
                    mma16816(acc[mt][nt], a[mt],
                             b[nt >> 1][(nt & 1) * 2], b[nt >> 1][(nt & 1) * 2 + 1]);
        }

        // ---- convert + store chunk c+1 into the other stage ----
        if (c + 1 < nch) {
            char* stg = smem + ((c + 1) & 1) * SM_STAGE;
            uint4 h0, l0, h1, l1;
            cvt8(av[0], av[1], h0, l0);
            cvt8(av[2], av[3], h1, l1);
            *(uint4*)(stg + OFF_AHI + eoff)      = h0;
            *(uint4*)(stg + OFF_AHI + eoff + 16) = h1;
            *(uint4*)(stg + OFF_ALO + eoff)      = l0;
            *(uint4*)(stg + OFF_ALO + eoff + 16) = l1;
            cvt8(wv[0], wv[1], h0, l0);
            cvt8(wv[2], wv[3], h1, l1);
            *(uint4*)(stg + OFF_BHI + eoff)      = h0;
            *(uint4*)(stg + OFF_BHI + eoff + 16) = h1;
            *(uint4*)(stg + OFF_BLO + eoff)      = l0;
            *(uint4*)(stg + OFF_BLO + eoff + 16) = l1;
        }
        __syncthreads();
    }

    // ---- epilogue ----
    const float alpha = (MODE == 3) ? a_ptr[0] : 0.f;
#pragma unroll
    for (int mt = 0; mt < 2; mt++) {
#pragma unroll
        for (int half = 0; half < 2; half++) {
            const int row = brow + m0 + mt * 16 + (lane >> 2) + half * 8;
            float* Crow = C + (size_t)row * ldc + bcol + n0 + (lane & 3) * 2;
            const float* brow_b = bias + bcol + n0 + (lane & 3) * 2;
#pragma unroll
            for (int nt = 0; nt < 8; nt++) {
                float v0 = acc[mt][nt][half * 2 + 0] + brow_b[nt * 8 + 0];
                float v1 = acc[mt][nt][half * 2 + 1] + brow_b[nt * 8 + 1];
                if (MODE == 1) {
                    v0 = v0 > 0.f ? v0 : 0.f;
                    v1 = v1 > 0.f ? v1 : 0.f;
                }
                if (MODE == 2) {
                    float2 old = *(float2*)(Crow + nt * 8);
                    v0 += old.x; v1 += old.y;
                }
                if (MODE == 3) {
                    float2 old = *(float2*)(Crow + nt * 8);
                    float l0 = (v0 >= 0.f) ? v0 : alpha * v0;
                    float l1 = (v1 >= 0.f) ? v1 : alpha * v1;
                    v0 = old.x - l0; v1 = old.y - l1;
                }
                *(float2*)(Crow + nt * 8) = make_float2(v0, v1);
            }
        }
    }
}

// -------------------- elementwise kernels (float4 vectorized) -------------
__global__ __launch_bounds__(256) void k_square(const float* __restrict__ x,
                                                float* __restrict__ q)
{
    const int i = blockIdx.x * blockDim.x + threadIdx.x;
    const int row = i / (FDIM / 4);
    const int c4  = i % (FDIM / 4);
    const float4 d = *(const float4*)(x + (size_t)row * XDIM + HDIM + B0DIM + c4 * 4);
    const float s = 0.78539816339744830962f;
    float4 o;
    o.x = s * d.x * d.x; o.y = s * d.y * d.y;
    o.z = s * d.z * d.z; o.w = s * d.w * d.w;
    *(float4*)(q + (size_t)row * FDIM + c4 * 4) = o;
}

__global__ __launch_bounds__(256) void k_mul(const float* __restrict__ a,
                                             const float* __restrict__ b,
                                             float* __restrict__ o)
{
    const int i = blockIdx.x * blockDim.x + threadIdx.x;
    const float4 av = ((const float4*)a)[i];
    const float4 bv = ((const float4*)b)[i];
    float4 ov;
    ov.x = av.x * bv.x; ov.y = av.y * bv.y;
    ov.z = av.z * bv.z; ov.w = av.w * bv.w;
    ((float4*)o)[i] = ov;
}

__global__ __launch_bounds__(256) void k_hid(const float* __restrict__ Aq,
                                             const float* __restrict__ q,
                                             const float* __restrict__ sumq,
                                             float* __restrict__ o)
{
    const int i = blockIdx.x * blockDim.x + threadIdx.x;
    const float4 a = ((const float4*)Aq)[i];
    const float4 b = ((const float4*)q)[i];
    const float4 c = ((const float4*)sumq)[i];
    float4 ov;
    ov.x = a.x * (b.x + c.x); ov.y = a.y * (b.y + c.y);
    ov.z = a.z * (b.z + c.z); ov.w = a.w * (b.w + c.w);
    ((float4*)o)[i] = ov;
}

__global__ __launch_bounds__(256) void k_comb(const float* __restrict__ h,
                                              const float* __restrict__ sumh,
                                              const float* __restrict__ rqh,
                                              const float* __restrict__ Dh,
                                              float* __restrict__ o)
{
    const int i = blockIdx.x * blockDim.x + threadIdx.x;
    const float4 a = ((const float4*)h)[i];
    const float4 b = ((const float4*)sumh)[i];
    const float4 c = ((const float4*)rqh)[i];
    const float4 d = ((const float4*)Dh)[i];
    float4 ov;
    ov.x = (a.x + b.x + c.x) * d.x; ov.y = (a.y + b.y + c.y) * d.y;
    ov.z = (a.z + b.z + c.z) * d.z; ov.w = (a.w + b.w + c.w) * d.w;
    ((float4*)o)[i] = ov;
}

// -------------------- driver ----------------------------------------------
extern "C" void kernel_launch(void* const* d_in, const int* in_sizes, int n_in,
                              void* d_out, int out_size)
{
    const float* x      = (const float*)d_in[0];
    const float* W_h0q  = (const float*)d_in[1];
    const float* b_h0q  = (const float*)d_in[2];
    const float* W_sq   = (const float*)d_in[3];
    const float* b_sq   = (const float*)d_in[4];
    const float* W_h0h  = (const float*)d_in[5];
    const float* b_h0h  = (const float*)d_in[6];
    const float* W_S    = (const float*)d_in[7];
    const float* b_S    = (const float*)d_in[8];
    const float* W_q0h  = (const float*)d_in[9];
    const float* b_q0h  = (const float*)d_in[10];
    const float* Wb_Aq  = (const float*)d_in[11];
    const float* bb_Aq  = (const float*)d_in[12];
    const float* Wb_Dh  = (const float*)d_in[13];
    const float* bb_Dh  = (const float*)d_in[14];
    const float* Wb_fh  = (const float*)d_in[15];
    const float* bb_fh  = (const float*)d_in[16];
    const float* Wb_hf  = (const float*)d_in[17];
    const float* bb_hf  = (const float*)d_in[18];
    const float* a_hf   = (const float*)d_in[19];
    const float* Wb_resq= (const float*)d_in[20];
    const float* bb_resq= (const float*)d_in[21];
    const float* W_out  = (const float*)d_in[22];
    const float* b_out  = (const float*)d_in[23];

    float *q, *sumq, *rS, *tb, *Aq, *sumh, *rqh, *Dh, *hb, *th;
    cudaGetSymbolAddress((void**)&q,    g_q);
    cudaGetSymbolAddress((void**)&sumq, g_sumq);
    cudaGetSymbolAddress((void**)&rS,   g_rS);
    cudaGetSymbolAddress((void**)&tb,   g_t);
    cudaGetSymbolAddress((void**)&Aq,   g_Aq);
    cudaGetSymbolAddress((void**)&sumh, g_sumh);
    cudaGetSymbolAddress((void**)&rqh,  g_rqh);
    cudaGetSymbolAddress((void**)&Dh,   g_Dh);
    cudaGetSymbolAddress((void**)&hb,   g_h);
    cudaGetSymbolAddress((void**)&th,   g_th);

    cudaFuncSetAttribute(gemm_db<0>, cudaFuncAttributeMaxDynamicSharedMemorySize, SMEM_TOTAL);
    cudaFuncSetAttribute(gemm_db<1>, cudaFuncAttributeMaxDynamicSharedMemorySize, SMEM_TOTAL);
    cudaFuncSetAttribute(gemm_db<2>, cudaFuncAttributeMaxDynamicSharedMemorySize, SMEM_TOTAL);
    cudaFuncSetAttribute(gemm_db<3>, cudaFuncAttributeMaxDynamicSharedMemorySize, SMEM_TOTAL);

    const dim3 gF(FDIM / BN, N_ROWS / BM);   // (16, 64)
    const dim3 gH(HDIM / BN, N_ROWS / BM);   // (8, 64)
    const int ewF = (N_ROWS * FDIM / 4) / 256;
    const int ewH = (N_ROWS * HDIM / 4) / 256;

    // ---- prologue ----
    gemm_db<0><<<gF, 256, SMEM_TOTAL>>>(x + HDIM, XDIM, W_h0q, b_h0q, sumq, FDIM, B0DIM, nullptr);
    gemm_db<2><<<gF, 256, SMEM_TOTAL>>>(x,        XDIM, W_sq,  b_sq,  sumq, FDIM, HDIM,  nullptr);
    gemm_db<0><<<gH, 256, SMEM_TOTAL>>>(x + HDIM, XDIM, W_h0h, b_h0h, sumh, HDIM, B0DIM, nullptr);
    gemm_db<1><<<gF, 256, SMEM_TOTAL>>>(x + HDIM + B0DIM, XDIM, W_S, b_S, rS, FDIM, FDIM, nullptr);
    k_square<<<ewF, 256>>>(x, q);
    gemm_db<0><<<gH, 256, SMEM_TOTAL>>>(q, FDIM, W_q0h, b_q0h, rqh, HDIM, FDIM, nullptr);

    // ---- 6 unrolled blocks ----
    for (int nb = 0; nb < NB; nb++) {
        const float* wAq   = Wb_Aq   + (size_t)nb * FDIM * FDIM;
        const float* bAq   = bb_Aq   + (size_t)nb * FDIM;
        const float* wDh   = Wb_Dh   + (size_t)nb * HDIM * FDIM;
        const float* bDh   = bb_Dh   + (size_t)nb * HDIM;
        const float* wfh   = Wb_fh   + (size_t)nb * HDIM * FDIM;
        const float* bfh   = bb_fh   + (size_t)nb * HDIM;
        const float* whf   = Wb_hf   + (size_t)nb * FDIM * HDIM;
        const float* bhf   = bb_hf   + (size_t)nb * FDIM;
        const float* wresq = Wb_resq + (size_t)nb * HDIM * FDIM;
        const float* bresq = bb_resq + (size_t)nb * HDIM;

        k_mul<<<ewF, 256>>>(q, rS, tb);
        gemm_db<0><<<gF, 256, SMEM_TOTAL>>>(tb, FDIM, wAq, bAq, Aq, FDIM, FDIM, nullptr);
        gemm_db<1><<<gH, 256, SMEM_TOTAL>>>(Aq, FDIM, wDh, bDh, Dh, HDIM, FDIM, nullptr);
        k_hid<<<ewF, 256>>>(Aq, q, sumq, tb);
        gemm_db<1><<<gH, 256, SMEM_TOTAL>>>(tb, FDIM, wfh, bfh, hb, HDIM, FDIM, nullptr);
        k_comb<<<ewH, 256>>>(hb, sumh, rqh, Dh, th);
        gemm_db<3><<<gF, 256, SMEM_TOTAL>>>(th, HDIM, whf, bhf, q, FDIM, HDIM, a_hf + nb);
        gemm_db<1><<<gH, 256, SMEM_TOTAL>>>(q, FDIM, wresq, bresq, rqh, HDIM, FDIM, nullptr);
    }

    // ---- output ----
    gemm_db<0><<<gF, 256, SMEM_TOTAL>>>(q, FDIM, W_out, b_out, (float*)d_out, ODIM, FDIM, nullptr);
}

// round 8
// speedup vs baseline: 1.4725x; 1.3981x over previous
#include <cuda_runtime.h>
#include <cuda_bf16.h>
#include <cstdint>

// Problem constants
#define N_ROWS 8192
#define HDIM   1024
#define B0DIM  64
#define FDIM   2048
#define ODIM   2048
#define XDIM   (HDIM + B0DIM + FDIM)   // 3136
#define NB     6

#define BM 128
#define BN 128
#define BK 32
#define SSTR 40   // bf16 elements per smem row (80B) -> conflict-free ldmatrix

// smem stage layout (bytes): 4 arrays of 128*40 bf16
#define OFF_AHI  0
#define OFF_ALO  10240
#define OFF_BHI  20480
#define OFF_BLO  30720
#define SM_STAGE 40960
#define SMEM_TOTAL (2 * SM_STAGE)   // 81920

// weight arena element offsets
#define NW_WS    (FDIM * FDIM)
#define NW_WSQ   (FDIM * HDIM)
#define NW_WH0Q  (FDIM * B0DIM)
#define NW_WH0H  (HDIM * B0DIM)
#define NW_WQ0H  (HDIM * FDIM)
#define NW_WOUT  (ODIM * FDIM)
#define NW_WAQ   (NB * FDIM * FDIM)
#define NW_WDH   (NB * HDIM * FDIM)
#define NW_WFH   (NB * HDIM * FDIM)
#define NW_WHF   (NB * FDIM * HDIM)
#define NW_WRESQ (NB * HDIM * FDIM)

#define O_WS    0
#define O_WSQ   (O_WS + NW_WS)
#define O_WH0Q  (O_WSQ + NW_WSQ)
#define O_WH0H  (O_WH0Q + NW_WH0Q)
#define O_WQ0H  (O_WH0H + NW_WH0H)
#define O_WOUT  (O_WQ0H + NW_WQ0H)
#define O_WAQ   (O_WOUT + NW_WOUT)
#define O_WDH   (O_WAQ + NW_WAQ)
#define O_WFH   (O_WDH + NW_WDH)
#define O_WHF   (O_WFH + NW_WFH)
#define O_WRESQ (O_WHF + NW_WHF)
#define NW_TOT  (O_WRESQ + NW_WRESQ)

#define NX   (N_ROWS * XDIM)
#define NF   (N_ROWS * FDIM)
#define NH   (N_ROWS * HDIM)

// -------------------- scratch (device globals; no allocs allowed) ---------
__device__ float g_q   [NF];
__device__ float g_sumq[NF];
__device__ float g_rS  [NF];
__device__ float g_Aq  [NF];
__device__ float g_sumh[NH];
__device__ float g_rqh [NH];
__device__ float g_Dh  [NH];
__device__ float g_h   [NH];

__device__ unsigned short g_whi[NW_TOT];
__device__ unsigned short g_wlo[NW_TOT];
__device__ unsigned short g_xhi[NX],  g_xlo[NX];
__device__ unsigned short g_qhi[NF],  g_qlo[NF];
__device__ unsigned short g_tbhi[NF], g_tblo[NF];
__device__ unsigned short g_Aqhi[NF], g_Aqlo[NF];
__device__ unsigned short g_thhi[NH], g_thlo[NH];

// -------------------- helpers ---------------------------------------------
__device__ __forceinline__ void ldsm_x4(uint32_t& r0, uint32_t& r1,
                                        uint32_t& r2, uint32_t& r3,
                                        uint32_t addr)
{
    asm volatile("ldmatrix.sync.aligned.m8n8.x4.shared.b16 {%0,%1,%2,%3}, [%4];"
                 : "=r"(r0), "=r"(r1), "=r"(r2), "=r"(r3) : "r"(addr));
}

__device__ __forceinline__ void mma16816(float* c, const uint32_t* a,
                                         uint32_t b0, uint32_t b1)
{
    asm volatile(
        "mma.sync.aligned.m16n8k16.row.col.f32.bf16.bf16.f32 "
        "{%0,%1,%2,%3}, {%4,%5,%6,%7}, {%8,%9}, {%0,%1,%2,%3};"
        : "+f"(c[0]), "+f"(c[1]), "+f"(c[2]), "+f"(c[3])
        : "r"(a[0]), "r"(a[1]), "r"(a[2]), "r"(a[3]), "r"(b0), "r"(b1));
}

__device__ __forceinline__ void cvt2(float x, float y, uint32_t& hi, uint32_t& lo)
{
    __nv_bfloat16 hx = __float2bfloat16(x);
    __nv_bfloat16 hy = __float2bfloat16(y);
    __nv_bfloat16 lx = __float2bfloat16(x - __bfloat162float(hx));
    __nv_bfloat16 ly = __float2bfloat16(y - __bfloat162float(hy));
    hi = (uint32_t(__bfloat16_as_ushort(hy)) << 16) | __bfloat16_as_ushort(hx);
    lo = (uint32_t(__bfloat16_as_ushort(ly)) << 16) | __bfloat16_as_ushort(lx);
}

__device__ __forceinline__ void split4(float4 v, uint2& hi, uint2& lo)
{
    uint32_t h0, l0, h1, l1;
    cvt2(v.x, v.y, h0, l0);
    cvt2(v.z, v.w, h1, l1);
    hi = make_uint2(h0, h1);
    lo = make_uint2(l0, l1);
}

__device__ __forceinline__ void cpa16(uint32_t dst, const void* src)
{
    asm volatile("cp.async.ca.shared.global [%0], [%1], 16;"
                 :: "r"(dst), "l"(src) : "memory");
}
#define CPA_COMMIT() asm volatile("cp.async.commit_group;" ::: "memory")
#define CPA_WAIT(n)  asm volatile("cp.async.wait_group %0;" :: "n"(n) : "memory")

// -------------------- pre-split bf16x3 tensor GEMM (cp.async pipelined) ---
// C = epi(A[M,K] @ W[Fout,K]^T + bias); A,W given as bf16 hi/lo planes.
// MODE 0: C = acc + b ; 1: relu ; 2: C += acc + b ; 3: C = C - leaky(acc+b)
// WB: also write bf16 hi/lo planes of the result (Chi/Clo).
template <int MODE, int WB>
__global__ __launch_bounds__(256, 2) void gemm_pc(
    const unsigned short* __restrict__ Ahi,
    const unsigned short* __restrict__ Alo, int lda,
    const unsigned short* __restrict__ Whi,
    const unsigned short* __restrict__ Wlo,     // ldw == K
    const float* __restrict__ bias,
    float* __restrict__ C,
    unsigned short* __restrict__ Chi,
    unsigned short* __restrict__ Clo, int ldc,
    int K,
    const float* __restrict__ a_ptr)
{
    extern __shared__ __align__(16) char smem[];
    const uint32_t sb = (uint32_t)__cvta_generic_to_shared(smem);

    const int t    = threadIdx.x;
    const int lane = t & 31;
    const int warp = t >> 5;
    const int wm   = warp >> 1;      // 0..3
    const int wn   = warp & 1;       // 0..1
    const int m0   = wm * 32;        // warp tile 32x64
    const int n0   = wn * 64;
    const int brow = blockIdx.y * BM;
    const int bcol = blockIdx.x * BN;

    // copy mapping: row = t>>1, kbase = (t&1)*16; two 16B chunks (k, k+8)
    const int crow  = t >> 1;
    const int kbase = (t & 1) * 16;
    const size_t aIdx = (size_t)(brow + crow) * lda + kbase;
    const size_t bIdx = (size_t)(bcol + crow) * K   + kbase;
    const uint32_t sOff = (uint32_t)(crow * SSTR + kbase) * 2u;

    float acc[2][8][4];
#pragma unroll
    for (int mt = 0; mt < 2; mt++)
#pragma unroll
        for (int nt = 0; nt < 8; nt++)
#pragma unroll
            for (int i = 0; i < 4; i++) acc[mt][nt][i] = 0.f;

    const int aoffA = ((m0 + (lane & 15)) * SSTR + ((lane >> 4) << 3)) * 2;
    const int aoffB = ((n0 + (lane & 7) + ((lane >> 4) << 3)) * SSTR
                       + (((lane >> 3) & 1) << 3)) * 2;

    const int nch = K / BK;

    // issue stage 0
    {
        const uint32_t sd = sb + sOff;
        cpa16(sd + OFF_AHI,      Ahi + aIdx);
        cpa16(sd + OFF_AHI + 16, Ahi + aIdx + 8);
        cpa16(sd + OFF_ALO,      Alo + aIdx);
        cpa16(sd + OFF_ALO + 16, Alo + aIdx + 8);
        cpa16(sd + OFF_BHI,      Whi + bIdx);
        cpa16(sd + OFF_BHI + 16, Whi + bIdx + 8);
        cpa16(sd + OFF_BLO,      Wlo + bIdx);
        cpa16(sd + OFF_BLO + 16, Wlo + bIdx + 8);
        CPA_COMMIT();
    }

    for (int c = 0; c < nch; c++) {
        if (c + 1 < nch) {
            const int k1 = (c + 1) * BK;
            const uint32_t sd = sb + ((c + 1) & 1) * SM_STAGE + sOff;
            cpa16(sd + OFF_AHI,      Ahi + aIdx + k1);
            cpa16(sd + OFF_AHI + 16, Ahi + aIdx + k1 + 8);
            cpa16(sd + OFF_ALO,      Alo + aIdx + k1);
            cpa16(sd + OFF_ALO + 16, Alo + aIdx + k1 + 8);
            cpa16(sd + OFF_BHI,      Whi + bIdx + k1);
            cpa16(sd + OFF_BHI + 16, Whi + bIdx + k1 + 8);
            cpa16(sd + OFF_BLO,      Wlo + bIdx + k1);
            cpa16(sd + OFF_BLO + 16, Wlo + bIdx + k1 + 8);
            CPA_COMMIT();
            CPA_WAIT(1);
        } else {
            CPA_WAIT(0);
        }
        __syncthreads();

        // ---- MMA from stage c&1; passes: Ahi*Bhi -> Alo*Bhi -> Ahi*Blo
        const uint32_t stgb = sb + (uint32_t)(c & 1) * SM_STAGE;
#pragma unroll
        for (int kk = 0; kk < BK; kk += 16) {
            uint32_t b[4][4];
#pragma unroll
            for (int g = 0; g < 4; g++)
                ldsm_x4(b[g][0], b[g][1], b[g][2], b[g][3],
                        stgb + OFF_BHI + (uint32_t)(aoffB + (g * 16 * SSTR + kk) * 2));
            uint32_t a[2][4];
#pragma unroll
            for (int mt = 0; mt < 2; mt++)
                ldsm_x4(a[mt][0], a[mt][1], a[mt][2], a[mt][3],
                        stgb + OFF_AHI + (uint32_t)(aoffA + (mt * 16 * SSTR + kk) * 2));
#pragma unroll
            for (int mt = 0; mt < 2; mt++)
#pragma unroll
                for (int nt = 0; nt < 8; nt++)
                    mma16816(acc[mt][nt], a[mt],
                             b[nt >> 1][(nt & 1) * 2], b[nt >> 1][(nt & 1) * 2 + 1]);
            uint32_t a2[2][4];
#pragma unroll
            for (int mt = 0; mt < 2; mt++)
                ldsm_x4(a2[mt][0], a2[mt][1], a2[mt][2], a2[mt][3],
                        stgb + OFF_ALO + (uint32_t)(aoffA + (mt * 16 * SSTR + kk) * 2));
#pragma unroll
            for (int mt = 0; mt < 2; mt++)
#pragma unroll
                for (int nt = 0; nt < 8; nt++)
                    mma16816(acc[mt][nt], a2[mt],
                             b[nt >> 1][(nt & 1) * 2], b[nt >> 1][(nt & 1) * 2 + 1]);
#pragma unroll
            for (int g = 0; g < 4; g++)
                ldsm_x4(b[g][0], b[g][1], b[g][2], b[g][3],
                        stgb + OFF_BLO + (uint32_t)(aoffB + (g * 16 * SSTR + kk) * 2));
#pragma unroll
            for (int mt = 0; mt < 2; mt++)
#pragma unroll
                for (int nt = 0; nt < 8; nt++)
                    mma16816(acc[mt][nt], a[mt],
                             b[nt >> 1][(nt & 1) * 2], b[nt >> 1][(nt & 1) * 2 + 1]);
        }
        __syncthreads();   // all reads of stage c&1 done before iter c+1 issues into it
    }

    // ---- epilogue ----
    const float alpha = (MODE == 3) ? a_ptr[0] : 0.f;
#pragma unroll
    for (int mt = 0; mt < 2; mt++) {
#pragma unroll
        for (int half = 0; half < 2; half++) {
            const int row = brow + m0 + mt * 16 + (lane >> 2) + half * 8;
            const int col0 = bcol + n0 + (lane & 3) * 2;
            float* Crow = C + (size_t)row * ldc + col0;
            const float* brow_b = bias + col0;
#pragma unroll
            for (int nt = 0; nt < 8; nt++) {
                float v0 = acc[mt][nt][half * 2 + 0] + brow_b[nt * 8 + 0];
                float v1 = acc[mt][nt][half * 2 + 1] + brow_b[nt * 8 + 1];
                if (MODE == 1) {
                    v0 = v0 > 0.f ? v0 : 0.f;
                    v1 = v1 > 0.f ? v1 : 0.f;
                }
                if (MODE == 2) {
                    float2 old = *(float2*)(Crow + nt * 8);
                    v0 += old.x; v1 += old.y;
                }
                if (MODE == 3) {
                    float2 old = *(float2*)(Crow + nt * 8);
                    float l0 = (v0 >= 0.f) ? v0 : alpha * v0;
                    float l1 = (v1 >= 0.f) ? v1 : alpha * v1;
                    v0 = old.x - l0; v1 = old.y - l1;
                }
                *(float2*)(Crow + nt * 8) = make_float2(v0, v1);
                if (WB) {
                    uint32_t hi, lo;
                    cvt2(v0, v1, hi, lo);
                    *(uint32_t*)(Chi + (size_t)row * ldc + col0 + nt * 8) = hi;
                    *(uint32_t*)(Clo + (size_t)row * ldc + col0 + nt * 8) = lo;
                }
            }
        }
    }
}

// -------------------- converters & elementwise (float4 vectorized) --------
__global__ __launch_bounds__(256) void k_split(const float* __restrict__ in,
                                               unsigned short* __restrict__ hi,
                                               unsigned short* __restrict__ lo,
                                               int n4)
{
    const int i = blockIdx.x * blockDim.x + threadIdx.x;
    if (i >= n4) return;
    float4 v = ((const float4*)in)[i];
    uint2 h, l;
    split4(v, h, l);
    ((uint2*)hi)[i] = h;
    ((uint2*)lo)[i] = l;
}

// q = (pi/4)*d^2 ; writes fp32 + planes
__global__ __launch_bounds__(256) void k_square(const float* __restrict__ x,
                                                float* __restrict__ q,
                                                unsigned short* __restrict__ qhi,
                                                unsigned short* __restrict__ qlo)
{
    const int i = blockIdx.x * blockDim.x + threadIdx.x;
    const int row = i / (FDIM / 4);
    const int c4  = i % (FDIM / 4);
    const float4 d = *(const float4*)(x + (size_t)row * XDIM + HDIM + B0DIM + c4 * 4);
    const float s = 0.78539816339744830962f;
    float4 o;
    o.x = s * d.x * d.x; o.y = s * d.y * d.y;
    o.z = s * d.z * d.z; o.w = s * d.w * d.w;
    const int oi = row * (FDIM / 4) + c4;
    ((float4*)q)[oi] = o;
    uint2 h, l; split4(o, h, l);
    ((uint2*)qhi)[oi] = h;
    ((uint2*)qlo)[oi] = l;
}

// tb_planes = q * rS
__global__ __launch_bounds__(256) void k_mul(const float* __restrict__ a,
                                             const float* __restrict__ b,
                                             unsigned short* __restrict__ ohi,
                                             unsigned short* __restrict__ olo)
{
    const int i = blockIdx.x * blockDim.x + threadIdx.x;
    const float4 av = ((const float4*)a)[i];
    const float4 bv = ((const float4*)b)[i];
    float4 o;
    o.x = av.x * bv.x; o.y = av.y * bv.y;
    o.z = av.z * bv.z; o.w = av.w * bv.w;
    uint2 h, l; split4(o, h, l);
    ((uint2*)ohi)[i] = h;
    ((uint2*)olo)[i] = l;
}

// tb_planes = Aq * (q + sumq)
__global__ __launch_bounds__(256) void k_hid(const float* __restrict__ Aq,
                                             const float* __restrict__ q,
                                             const float* __restrict__ sumq,
                                             unsigned short* __restrict__ ohi,
                                             unsigned short* __restrict__ olo)
{
    const int i = blockIdx.x * blockDim.x + threadIdx.x;
    const float4 a = ((const float4*)Aq)[i];
    const float4 b = ((const float4*)q)[i];
    const float4 c = ((const float4*)sumq)[i];
    float4 o;
    o.x = a.x * (b.x + c.x); o.y = a.y * (b.y + c.y);
    o.z = a.z * (b.z + c.z); o.w = a.w * (b.w + c.w);
    uint2 h, l; split4(o, h, l);
    ((uint2*)ohi)[i] = h;
    ((uint2*)olo)[i] = l;
}

// th_planes = (h + sumh + rqh) * Dh
__global__ __launch_bounds__(256) void k_comb(const float* __restrict__ h,
                                              const float* __restrict__ sumh,
                                              const float* __restrict__ rqh,
                                              const float* __restrict__ Dh,
                                              unsigned short* __restrict__ ohi,
                                              unsigned short* __restrict__ olo)
{
    const int i = blockIdx.x * blockDim.x + threadIdx.x;
    const float4 a = ((const float4*)h)[i];
    const float4 b = ((const float4*)sumh)[i];
    const float4 c = ((const float4*)rqh)[i];
    const float4 d = ((const float4*)Dh)[i];
    float4 o;
    o.x = (a.x + b.x + c.x) * d.x; o.y = (a.y + b.y + c.y) * d.y;
    o.z = (a.z + b.z + c.z) * d.z; o.w = (a.w + b.w + c.w) * d.w;
    uint2 hh, ll; split4(o, hh, ll);
    ((uint2*)ohi)[i] = hh;
    ((uint2*)olo)[i] = ll;
}

// -------------------- driver ----------------------------------------------
extern "C" void kernel_launch(void* const* d_in, const int* in_sizes, int n_in,
                              void* d_out, int out_size)
{
    const float* x      = (const float*)d_in[0];
    const float* W_h0q  = (const float*)d_in[1];
    const float* b_h0q  = (const float*)d_in[2];
    const float* W_sq   = (const float*)d_in[3];
    const float* b_sq   = (const float*)d_in[4];
    const float* W_h0h  = (const float*)d_in[5];
    const float* b_h0h  = (const float*)d_in[6];
    const float* W_S    = (const float*)d_in[7];
    const float* b_S    = (const float*)d_in[8];
    const float* W_q0h  = (const float*)d_in[9];
    const float* b_q0h  = (const float*)d_in[10];
    const float* Wb_Aq  = (const float*)d_in[11];
    const float* bb_Aq  = (const float*)d_in[12];
    const float* Wb_Dh  = (const float*)d_in[13];
    const float* bb_Dh  = (const float*)d_in[14];
    const float* Wb_fh  = (const float*)d_in[15];
    const float* bb_fh  = (const float*)d_in[16];
    const float* Wb_hf  = (const float*)d_in[17];
    const float* bb_hf  = (const float*)d_in[18];
    const float* a_hf   = (const float*)d_in[19];
    const float* Wb_resq= (const float*)d_in[20];
    const float* bb_resq= (const float*)d_in[21];
    const float* W_out  = (const float*)d_in[22];
    const float* b_out  = (const float*)d_in[23];

    float *q, *sumq, *rS, *Aq, *sumh, *rqh, *Dh, *hb;
    cudaGetSymbolAddress((void**)&q,    g_q);
    cudaGetSymbolAddress((void**)&sumq, g_sumq);
    cudaGetSymbolAddress((void**)&rS,   g_rS);
    cudaGetSymbolAddress((void**)&Aq,   g_Aq);
    cudaGetSymbolAddress((void**)&sumh, g_sumh);
    cudaGetSymbolAddress((void**)&rqh,  g_rqh);
    cudaGetSymbolAddress((void**)&Dh,   g_Dh);
    cudaGetSymbolAddress((void**)&hb,   g_h);

    unsigned short *whi, *wlo, *xhi, *xlo, *qhi, *qlo, *tbhi, *tblo,
                   *aqhi, *aqlo, *thhi, *thlo;
    cudaGetSymbolAddress((void**)&whi,  g_whi);
    cudaGetSymbolAddress((void**)&wlo,  g_wlo);
    cudaGetSymbolAddress((void**)&xhi,  g_xhi);
    cudaGetSymbolAddress((void**)&xlo,  g_xlo);
    cudaGetSymbolAddress((void**)&qhi,  g_qhi);
    cudaGetSymbolAddress((void**)&qlo,  g_qlo);
    cudaGetSymbolAddress((void**)&tbhi, g_tbhi);
    cudaGetSymbolAddress((void**)&tblo, g_tblo);
    cudaGetSymbolAddress((void**)&aqhi, g_Aqhi);
    cudaGetSymbolAddress((void**)&aqlo, g_Aqlo);
    cudaGetSymbolAddress((void**)&thhi, g_thhi);
    cudaGetSymbolAddress((void**)&thlo, g_thlo);

    cudaFuncSetAttribute(gemm_pc<0,0>, cudaFuncAttributeMaxDynamicSharedMemorySize, SMEM_TOTAL);
    cudaFuncSetAttribute(gemm_pc<0,1>, cudaFuncAttributeMaxDynamicSharedMemorySize, SMEM_TOTAL);
    cudaFuncSetAttribute(gemm_pc<1,0>, cudaFuncAttributeMaxDynamicSharedMemorySize, SMEM_TOTAL);
    cudaFuncSetAttribute(gemm_pc<2,0>, cudaFuncAttributeMaxDynamicSharedMemorySize, SMEM_TOTAL);
    cudaFuncSetAttribute(gemm_pc<3,1>, cudaFuncAttributeMaxDynamicSharedMemorySize, SMEM_TOTAL);

    // ---- one-time (per launch) weight & x splitting ----
    auto SPL = [&](const float* src, unsigned short* hi, unsigned short* lo, int n) {
        const int n4 = n / 4;
        k_split<<<(n4 + 255) / 256, 256>>>(src, hi, lo, n4);
    };
    SPL(W_S,    whi + O_WS,    wlo + O_WS,    NW_WS);
    SPL(W_sq,   whi + O_WSQ,   wlo + O_WSQ,   NW_WSQ);
    SPL(W_h0q,  whi + O_WH0Q,  wlo + O_WH0Q,  NW_WH0Q);
    SPL(W_h0h,  whi + O_WH0H,  wlo + O_WH0H,  NW_WH0H);
    SPL(W_q0h,  whi + O_WQ0H,  wlo + O_WQ0H,  NW_WQ0H);
    SPL(W_out,  whi + O_WOUT,  wlo + O_WOUT,  NW_WOUT);
    SPL(Wb_Aq,  whi + O_WAQ,   wlo + O_WAQ,   NW_WAQ);
    SPL(Wb_Dh,  whi + O_WDH,   wlo + O_WDH,   NW_WDH);
    SPL(Wb_fh,  whi + O_WFH,   wlo + O_WFH,   NW_WFH);
    SPL(Wb_hf,  whi + O_WHF,   wlo + O_WHF,   NW_WHF);
    SPL(Wb_resq,whi + O_WRESQ, wlo + O_WRESQ, NW_WRESQ);
    SPL(x,      xhi,           xlo,           NX);

    const dim3 gF(FDIM / BN, N_ROWS / BM);   // (16, 64)
    const dim3 gH(HDIM / BN, N_ROWS / BM);   // (8, 64)
    const int ewF = (N_ROWS * FDIM / 4) / 256;
    const int ewH = (N_ROWS * HDIM / 4) / 256;

    // ---- prologue ----
    // sum_q_const = h0@W_h0q^T + b  +  s@W_sq^T + b
    gemm_pc<0,0><<<gF, 256, SMEM_TOTAL>>>(xhi + HDIM, xlo + HDIM, XDIM,
        whi + O_WH0Q, wlo + O_WH0Q, b_h0q, sumq, nullptr, nullptr, FDIM, B0DIM, nullptr);
    gemm_pc<2,0><<<gF, 256, SMEM_TOTAL>>>(xhi, xlo, XDIM,
        whi + O_WSQ, wlo + O_WSQ, b_sq, sumq, nullptr, nullptr, FDIM, HDIM, nullptr);
    // sum_h_const
    gemm_pc<0,0><<<gH, 256, SMEM_TOTAL>>>(xhi + HDIM, xlo + HDIM, XDIM,
        whi + O_WH0H, wlo + O_WH0H, b_h0h, sumh, nullptr, nullptr, HDIM, B0DIM, nullptr);
    // res_S_q = relu(d@W_S^T + b)
    gemm_pc<1,0><<<gF, 256, SMEM_TOTAL>>>(xhi + HDIM + B0DIM, xlo + HDIM + B0DIM, XDIM,
        whi + O_WS, wlo + O_WS, b_S, rS, nullptr, nullptr, FDIM, FDIM, nullptr);
    // q = pi/4 * d^2
    k_square<<<ewF, 256>>>(x, q, qhi, qlo);
    // res_q_h
    gemm_pc<0,0><<<gH, 256, SMEM_TOTAL>>>(qhi, qlo, FDIM,
        whi + O_WQ0H, wlo + O_WQ0H, b_q0h, rqh, nullptr, nullptr, HDIM, FDIM, nullptr);

    // ---- 6 unrolled blocks ----
    for (int nb = 0; nb < NB; nb++) {
        const size_t oAq   = O_WAQ   + (size_t)nb * FDIM * FDIM;
        const size_t oDh   = O_WDH   + (size_t)nb * HDIM * FDIM;
        const size_t oFh   = O_WFH   + (size_t)nb * HDIM * FDIM;
        const size_t oHf   = O_WHF   + (size_t)nb * FDIM * HDIM;
        const size_t oResq = O_WRESQ + (size_t)nb * HDIM * FDIM;
        const float* bAq   = bb_Aq   + (size_t)nb * FDIM;
        const float* bDh   = bb_Dh   + (size_t)nb * HDIM;
        const float* bfh   = bb_fh   + (size_t)nb * HDIM;
        const float* bhf   = bb_hf   + (size_t)nb * FDIM;
        const float* bresq = bb_resq + (size_t)nb * HDIM;

        // tb = q * rS ; A_q = tb@W_Aq^T + b  (Aq fp32 + planes)
        k_mul<<<ewF, 256>>>(q, rS, tbhi, tblo);
        gemm_pc<0,1><<<gF, 256, SMEM_TOTAL>>>(tbhi, tblo, FDIM,
            whi + oAq, wlo + oAq, bAq, Aq, aqhi, aqlo, FDIM, FDIM, nullptr);
        // D_h = relu(A_q@W_Dh^T + b)
        gemm_pc<1,0><<<gH, 256, SMEM_TOTAL>>>(aqhi, aqlo, FDIM,
            whi + oDh, wlo + oDh, bDh, Dh, nullptr, nullptr, HDIM, FDIM, nullptr);
        // tb = A_q * (q + sumq) ; h = relu(tb@W_fh^T + b)
        k_hid<<<ewF, 256>>>(Aq, q, sumq, tbhi, tblo);
        gemm_pc<1,0><<<gH, 256, SMEM_TOTAL>>>(tbhi, tblo, FDIM,
            whi + oFh, wlo + oFh, bfh, hb, nullptr, nullptr, HDIM, FDIM, nullptr);
        // th = (h + sumh + rqh) * D_h ; q = q - leaky(th@W_hf^T + b)  (q fp32 + planes)
        k_comb<<<ewH, 256>>>(hb, sumh, rqh, Dh, thhi, thlo);
        gemm_pc<3,1><<<gF, 256, SMEM_TOTAL>>>(thhi, thlo, HDIM,
            whi + oHf, wlo + oHf, bhf, q, qhi, qlo, FDIM, HDIM, a_hf + nb);
        // res_q_h = relu(q@W_resq^T + b)
        gemm_pc<1,0><<<gH, 256, SMEM_TOTAL>>>(qhi, qlo, FDIM,
            whi + oResq, wlo + oResq, bresq, rqh, nullptr, nullptr, HDIM, FDIM, nullptr);
    }

    // ---- output ----
    gemm_pc<0,0><<<gF, 256, SMEM_TOTAL>>>(qhi, qlo, FDIM,
        whi + O_WOUT, wlo + O_WOUT, b_out, (float*)d_out, nullptr, nullptr, ODIM, FDIM, nullptr);
}

// round 11
// speedup vs baseline: 1.5086x; 1.0245x over previous
#include <cuda_runtime.h>
#include <cuda_bf16.h>
#include <cstdint>

// Problem constants
#define N_ROWS 8192
#define HDIM   1024
#define B0DIM  64
#define FDIM   2048
#define ODIM   2048
#define XDIM   (HDIM + B0DIM + FDIM)   // 3136
#define NB     6

#define BM 128
#define BN 128
#define BK 32

// smem: rows are exactly 64B (32 bf16); segment-XOR swizzle kills conflicts.
// swizzled byte offset of (row r, 16B-segment s): r*64 + ((s ^ ((r>>1)&3))<<4)
#define OFF_AHI  0
#define OFF_ALO  8192
#define OFF_BHI  16384
#define OFF_BLO  24576
#define SM_STAGE 32768
#define NSTG     3
#define SMEM_TOTAL (NSTG * SM_STAGE)   // 98304 -> 2 CTAs/SM

// weight arena element offsets
#define NW_WS    (FDIM * FDIM)
#define NW_WSQ   (FDIM * HDIM)
#define NW_WH0Q  (FDIM * B0DIM)
#define NW_WH0H  (HDIM * B0DIM)
#define NW_WQ0H  (HDIM * FDIM)
#define NW_WOUT  (ODIM * FDIM)
#define NW_WAQ   (NB * FDIM * FDIM)
#define NW_WDH   (NB * HDIM * FDIM)
#define NW_WFH   (NB * HDIM * FDIM)
#define NW_WHF   (NB * FDIM * HDIM)
#define NW_WRESQ (NB * HDIM * FDIM)

#define O_WS    0
#define O_WSQ   (O_WS + NW_WS)
#define O_WH0Q  (O_WSQ + NW_WSQ)
#define O_WH0H  (O_WH0Q + NW_WH0Q)
#define O_WQ0H  (O_WH0H + NW_WH0H)
#define O_WOUT  (O_WQ0H + NW_WQ0H)
#define O_WAQ   (O_WOUT + NW_WOUT)
#define O_WDH   (O_WAQ + NW_WAQ)
#define O_WFH   (O_WDH + NW_WDH)
#define O_WHF   (O_WFH + NW_WFH)
#define O_WRESQ (O_WHF + NW_WHF)
#define NW_TOT  (O_WRESQ + NW_WRESQ)

#define NX   (N_ROWS * XDIM)
#define NF   (N_ROWS * FDIM)
#define NH   (N_ROWS * HDIM)

// -------------------- scratch (device globals; no allocs allowed) ---------
__device__ float g_q   [NF];
__device__ float g_sumq[NF];
__device__ float g_rS  [NF];
__device__ float g_Aq  [NF];
__device__ float g_sumh[NH];
__device__ float g_rqh [NH];
__device__ float g_Dh  [NH];
__device__ float g_h   [NH];

__device__ unsigned short g_whi[NW_TOT];
__device__ unsigned short g_wlo[NW_TOT];
__device__ unsigned short g_xhi[NX],  g_xlo[NX];
__device__ unsigned short g_qhi[NF],  g_qlo[NF];
__device__ unsigned short g_tbhi[NF], g_tblo[NF];
__device__ unsigned short g_Aqhi[NF], g_Aqlo[NF];
__device__ unsigned short g_thhi[NH], g_thlo[NH];

// -------------------- helpers ---------------------------------------------
__device__ __forceinline__ uint32_t swz(int row, int seg)
{
    return (uint32_t)(row * 64 + ((seg ^ ((row >> 1) & 3)) << 4));
}

__device__ __forceinline__ void ldsm_x4(uint32_t& r0, uint32_t& r1,
                                        uint32_t& r2, uint32_t& r3,
                                        uint32_t addr)
{
    asm volatile("ldmatrix.sync.aligned.m8n8.x4.shared.b16 {%0,%1,%2,%3}, [%4];"
                 : "=r"(r0), "=r"(r1), "=r"(r2), "=r"(r3) : "r"(addr));
}

__device__ __forceinline__ void mma16816(float* c, const uint32_t* a,
                                         uint32_t b0, uint32_t b1)
{
    asm volatile(
        "mma.sync.aligned.m16n8k16.row.col.f32.bf16.bf16.f32 "
        "{%0,%1,%2,%3}, {%4,%5,%6,%7}, {%8,%9}, {%0,%1,%2,%3};"
        : "+f"(c[0]), "+f"(c[1]), "+f"(c[2]), "+f"(c[3])
        : "r"(a[0]), "r"(a[1]), "r"(a[2]), "r"(a[3]), "r"(b0), "r"(b1));
}

__device__ __forceinline__ void cvt2(float x, float y, uint32_t& hi, uint32_t& lo)
{
    __nv_bfloat16 hx = __float2bfloat16(x);
    __nv_bfloat16 hy = __float2bfloat16(y);
    __nv_bfloat16 lx = __float2bfloat16(x - __bfloat162float(hx));
    __nv_bfloat16 ly = __float2bfloat16(y - __bfloat162float(hy));
    hi = (uint32_t(__bfloat16_as_ushort(hy)) << 16) | __bfloat16_as_ushort(hx);
    lo = (uint32_t(__bfloat16_as_ushort(ly)) << 16) | __bfloat16_as_ushort(lx);
}

__device__ __forceinline__ void split4(float4 v, uint2& hi, uint2& lo)
{
    uint32_t h0, l0, h1, l1;
    cvt2(v.x, v.y, h0, l0);
    cvt2(v.z, v.w, h1, l1);
    hi = make_uint2(h0, h1);
    lo = make_uint2(l0, l1);
}

__device__ __forceinline__ void cpa16(uint32_t dst, const void* src)
{
    asm volatile("cp.async.cg.shared.global [%0], [%1], 16;"
                 :: "r"(dst), "l"(src) : "memory");
}
#define CPA_COMMIT() asm volatile("cp.async.commit_group;" ::: "memory")
#define CPA_WAIT(n)  asm volatile("cp.async.wait_group %0;" :: "n"(n) : "memory")

// -------------------- pre-split bf16x3 tensor GEMM (3-stage pipeline) -----
// C = epi(A[M,K] @ W[Fout,K]^T + bias); A,W given as bf16 hi/lo planes.
// MODE 0: C = acc + b ; 1: relu ; 2: C += acc + b ; 3: C = C - leaky(acc+b)
// WB: also write bf16 hi/lo planes of the result (Chi/Clo).
template <int MODE, int WB>
__global__ __launch_bounds__(256, 2) void gemm_pc(
    const unsigned short* __restrict__ Ahi,
    const unsigned short* __restrict__ Alo, int lda,
    const unsigned short* __restrict__ Whi,
    const unsigned short* __restrict__ Wlo,     // ldw == K
    const float* __restrict__ bias,
    float* __restrict__ C,
    unsigned short* __restrict__ Chi,
    unsigned short* __restrict__ Clo, int ldc,
    int K,
    const float* __restrict__ a_ptr)
{
    extern __shared__ __align__(16) char smem[];
    const uint32_t sb = (uint32_t)__cvta_generic_to_shared(smem);

    const int t    = threadIdx.x;
    const int lane = t & 31;
    const int warp = t >> 5;
    const int wm   = warp >> 1;      // 0..3
    const int wn   = warp & 1;       // 0..1
    const int m0   = wm * 32;        // warp tile 32x64
    const int n0   = wn * 64;
    const int brow = blockIdx.y * BM;
    const int bcol = blockIdx.x * BN;

    // copy mapping: row = t>>1, k-half = (t&1)*16 elements = segments {2h, 2h+1}
    const int crow = t >> 1;
    const int s0   = (t & 1) * 2;
    const size_t aIdx = (size_t)(brow + crow) * lda + (t & 1) * 16;
    const size_t bIdx = (size_t)(bcol + crow) * K   + (t & 1) * 16;
    const uint32_t d0 = swz(crow, s0);
    const uint32_t d1 = swz(crow, s0 + 1);

    float acc[2][8][4];
#pragma unroll
    for (int mt = 0; mt < 2; mt++)
#pragma unroll
        for (int nt = 0; nt < 8; nt++)
#pragma unroll
            for (int i = 0; i < 4; i++) acc[mt][nt][i] = 0.f;

    // per-lane ldmatrix row/segment bases
    const int rA0    = m0 + (lane & 15);
    const int sAbase = lane >> 4;                       // 0/1
    const int rB0    = n0 + (lane & 7) + ((lane >> 4) << 3);
    const int sBbase = (lane >> 3) & 1;                 // 0/1

    const int nch = K / BK;

    // issue stage 0 (chunk 0)
    {
        const uint32_t sd = sb;
        cpa16(sd + OFF_AHI + d0, Ahi + aIdx);
        cpa16(sd + OFF_AHI + d1, Ahi + aIdx + 8);
        cpa16(sd + OFF_ALO + d0, Alo + aIdx);
        cpa16(sd + OFF_ALO + d1, Alo + aIdx + 8);
        cpa16(sd + OFF_BHI + d0, Whi + bIdx);
        cpa16(sd + OFF_BHI + d1, Whi + bIdx + 8);
        cpa16(sd + OFF_BLO + d0, Wlo + bIdx);
        cpa16(sd + OFF_BLO + d1, Wlo + bIdx + 8);
        CPA_COMMIT();
    }

    int stg = 0;       // stage index of chunk c
    for (int c = 0; c < nch; c++) {
        if (c + 1 < nch) {
            const int k1 = (c + 1) * BK;
            int stg1 = stg + 1; if (stg1 == NSTG) stg1 = 0;
            const uint32_t sd = sb + (uint32_t)stg1 * SM_STAGE;
            cpa16(sd + OFF_AHI + d0, Ahi + aIdx + k1);
            cpa16(sd + OFF_AHI + d1, Ahi + aIdx + k1 + 8);
            cpa16(sd + OFF_ALO + d0, Alo + aIdx + k1);
            cpa16(sd + OFF_ALO + d1, Alo + aIdx + k1 + 8);
            cpa16(sd + OFF_BHI + d0, Whi + bIdx + k1);
            cpa16(sd + OFF_BHI + d1, Whi + bIdx + k1 + 8);
            cpa16(sd + OFF_BLO + d0, Wlo + bIdx + k1);
            cpa16(sd + OFF_BLO + d1, Wlo + bIdx + k1 + 8);
            CPA_COMMIT();
            CPA_WAIT(1);
        } else {
            CPA_WAIT(0);
        }
        __syncthreads();   // single barrier per chunk (3-stage ring makes this safe)

        // ---- MMA from stage stg; passes: Ahi*Bhi -> Alo*Bhi -> Ahi*Blo
        const uint32_t stgb = sb + (uint32_t)stg * SM_STAGE;
#pragma unroll
        for (int kk = 0; kk < BK; kk += 16) {
            const int sA = sAbase + (kk >> 3);
            const int sB = sBbase + (kk >> 3);
            uint32_t b[4][4];
#pragma unroll
            for (int g = 0; g < 4; g++)
                ldsm_x4(b[g][0], b[g][1], b[g][2], b[g][3],
                        stgb + OFF_BHI + swz(rB0 + g * 16, sB));
            uint32_t a[2][4];
#pragma unroll
            for (int mt = 0; mt < 2; mt++)
                ldsm_x4(a[mt][0], a[mt][1], a[mt][2], a[mt][3],
                        stgb + OFF_AHI + swz(rA0 + mt * 16, sA));
#pragma unroll
            for (int mt = 0; mt < 2; mt++)
#pragma unroll
                for (int nt = 0; nt < 8; nt++)
                    mma16816(acc[mt][nt], a[mt],
                             b[nt >> 1][(nt & 1) * 2], b[nt >> 1][(nt & 1) * 2 + 1]);
            uint32_t a2[2][4];
#pragma unroll
            for (int mt = 0; mt < 2; mt++)
                ldsm_x4(a2[mt][0], a2[mt][1], a2[mt][2], a2[mt][3],
                        stgb + OFF_ALO + swz(rA0 + mt * 16, sA));
#pragma unroll
            for (int mt = 0; mt < 2; mt++)
#pragma unroll
                for (int nt = 0; nt < 8; nt++)
                    mma16816(acc[mt][nt], a2[mt],
                             b[nt >> 1][(nt & 1) * 2], b[nt >> 1][(nt & 1) * 2 + 1]);
#pragma unroll
            for (int g = 0; g < 4; g++)
                ldsm_x4(b[g][0], b[g][1], b[g][2], b[g][3],
                        stgb + OFF_BLO + swz(rB0 + g * 16, sB));
#pragma unroll
            for (int mt = 0; mt < 2; mt++)
#pragma unroll
                for (int nt = 0; nt < 8; nt++)
                    mma16816(acc[mt][nt], a[mt],
                             b[nt >> 1][(nt & 1) * 2], b[nt >> 1][(nt & 1) * 2 + 1]);
        }
        if (++stg == NSTG) stg = 0;
    }

    // ---- epilogue ----
    const float alpha = (MODE == 3) ? a_ptr[0] : 0.f;
#pragma unroll
    for (int mt = 0; mt < 2; mt++) {
#pragma unroll
        for (int half = 0; half < 2; half++) {
            const int row = brow + m0 + mt * 16 + (lane >> 2) + half * 8;
            const int col0 = bcol + n0 + (lane & 3) * 2;
            float* Crow = C + (size_t)row * ldc + col0;
            const float* brow_b = bias + col0;
#pragma unroll
            for (int nt = 0; nt < 8; nt++) {
                float v0 = acc[mt][nt][half * 2 + 0] + brow_b[nt * 8 + 0];
                float v1 = acc[mt][nt][half * 2 + 1] + brow_b[nt * 8 + 1];
                if (MODE == 1) {
                    v0 = v0 > 0.f ? v0 : 0.f;
                    v1 = v1 > 0.f ? v1 : 0.f;
                }
                if (MODE == 2) {
                    float2 old = *(float2*)(Crow + nt * 8);
                    v0 += old.x; v1 += old.y;
                }
                if (MODE == 3) {
                    float2 old = *(float2*)(Crow + nt * 8);
                    float l0 = (v0 >= 0.f) ? v0 : alpha * v0;
                    float l1 = (v1 >= 0.f) ? v1 : alpha * v1;
                    v0 = old.x - l0; v1 = old.y - l1;
                }
                *(float2*)(Crow + nt * 8) = make_float2(v0, v1);
                if (WB) {
                    uint32_t hi, lo;
                    cvt2(v0, v1, hi, lo);
                    *(uint32_t*)(Chi + (size_t)row * ldc + col0 + nt * 8) = hi;
                    *(uint32_t*)(Clo + (size_t)row * ldc + col0 + nt * 8) = lo;
                }
            }
        }
    }
}

// -------------------- converters & elementwise (float4 vectorized) --------
__global__ __launch_bounds__(256) void k_split(const float* __restrict__ in,
                                               unsigned short* __restrict__ hi,
                                               unsigned short* __restrict__ lo,
                                               int n4)
{
    const int i = blockIdx.x * blockDim.x + threadIdx.x;
    if (i >= n4) return;
    float4 v = ((const float4*)in)[i];
    uint2 h, l;
    split4(v, h, l);
    ((uint2*)hi)[i] = h;
    ((uint2*)lo)[i] = l;
}

// q = (pi/4)*d^2 ; writes fp32 + planes
__global__ __launch_bounds__(256) void k_square(const float* __restrict__ x,
                                                float* __restrict__ q,
                                                unsigned short* __restrict__ qhi,
                                                unsigned short* __restrict__ qlo)
{
    const int i = blockIdx.x * blockDim.x + threadIdx.x;
    const int row = i / (FDIM / 4);
    const int c4  = i % (FDIM / 4);
    const float4 d = *(const float4*)(x + (size_t)row * XDIM + HDIM + B0DIM + c4 * 4);
    const float s = 0.78539816339744830962f;
    float4 o;
    o.x = s * d.x * d.x; o.y = s * d.y * d.y;
    o.z = s * d.z * d.z; o.w = s * d.w * d.w;
    const int oi = row * (FDIM / 4) + c4;
    ((float4*)q)[oi] = o;
    uint2 h, l; split4(o, h, l);
    ((uint2*)qhi)[oi] = h;
    ((uint2*)qlo)[oi] = l;
}

// tb_planes = q * rS
__global__ __launch_bounds__(256) void k_mul(const float* __restrict__ a,
                                             const float* __restrict__ b,
                                             unsigned short* __restrict__ ohi,
                                             unsigned short* __restrict__ olo)
{
    const int i = blockIdx.x * blockDim.x + threadIdx.x;
    const float4 av = ((const float4*)a)[i];
    const float4 bv = ((const float4*)b)[i];
    float4 o;
    o.x = av.x * bv.x; o.y = av.y * bv.y;
    o.z = av.z * bv.z; o.w = av.w * bv.w;
    uint2 h, l; split4(o, h, l);
    ((uint2*)ohi)[i] = h;
    ((uint2*)olo)[i] = l;
}

// tb_planes = Aq * (q + sumq)
__global__ __launch_bounds__(256) void k_hid(const float* __restrict__ Aq,
                                             const float* __restrict__ q,
                                             const float* __restrict__ sumq,
                                             unsigned short* __restrict__ ohi,
                                             unsigned short* __restrict__ olo)
{
    const int i = blockIdx.x * blockDim.x + threadIdx.x;
    const float4 a = ((const float4*)Aq)[i];
    const float4 b = ((const float4*)q)[i];
    const float4 c = ((const float4*)sumq)[i];
    float4 o;
    o.x = a.x * (b.x + c.x); o.y = a.y * (b.y + c.y);
    o.z = a.z * (b.z + c.z); o.w = a.w * (b.w + c.w);
    uint2 h, l; split4(o, h, l);
    ((uint2*)ohi)[i] = h;
    ((uint2*)olo)[i] = l;
}

// th_planes = (h + sumh + rqh) * Dh
__global__ __launch_bounds__(256) void k_comb(const float* __restrict__ h,
                                              const float* __restrict__ sumh,
                                              const float* __restrict__ rqh,
                                              const float* __restrict__ Dh,
                                              unsigned short* __restrict__ ohi,
                                              unsigned short* __restrict__ olo)
{
    const int i = blockIdx.x * blockDim.x + threadIdx.x;
    const float4 a = ((const float4*)h)[i];
    const float4 b = ((const float4*)sumh)[i];
    const float4 c = ((const float4*)rqh)[i];
    const float4 d = ((const float4*)Dh)[i];
    float4 o;
    o.x = (a.x + b.x + c.x) * d.x; o.y = (a.y + b.y + c.y) * d.y;
    o.z = (a.z + b.z + c.z) * d.z; o.w = (a.w + b.w + c.w) * d.w;
    uint2 hh, ll; split4(o, hh, ll);
    ((uint2*)ohi)[i] = hh;
    ((uint2*)olo)[i] = ll;
}

// -------------------- driver ----------------------------------------------
extern "C" void kernel_launch(void* const* d_in, const int* in_sizes, int n_in,
                              void* d_out, int out_size)
{
    const float* x      = (const float*)d_in[0];
    const float* W_h0q  = (const float*)d_in[1];
    const float* b_h0q  = (const float*)d_in[2];
    const float* W_sq   = (const float*)d_in[3];
    const float* b_sq   = (const float*)d_in[4];
    const float* W_h0h  = (const float*)d_in[5];
    const float* b_h0h  = (const float*)d_in[6];
    const float* W_S    = (const float*)d_in[7];
    const float* b_S    = (const float*)d_in[8];
    const float* W_q0h  = (const float*)d_in[9];
    const float* b_q0h  = (const float*)d_in[10];
    const float* Wb_Aq  = (const float*)d_in[11];
    const float* bb_Aq  = (const float*)d_in[12];
    const float* Wb_Dh  = (const float*)d_in[13];
    const float* bb_Dh  = (const float*)d_in[14];
    const float* Wb_fh  = (const float*)d_in[15];
    const float* bb_fh  = (const float*)d_in[16];
    const float* Wb_hf  = (const float*)d_in[17];
    const float* bb_hf  = (const float*)d_in[18];
    const float* a_hf   = (const float*)d_in[19];
    const float* Wb_resq= (const float*)d_in[20];
    const float* bb_resq= (const float*)d_in[21];
    const float* W_out  = (const float*)d_in[22];
    const float* b_out  = (const float*)d_in[23];

    float *q, *sumq, *rS, *Aq, *sumh, *rqh, *Dh, *hb;
    cudaGetSymbolAddress((void**)&q,    g_q);
    cudaGetSymbolAddress((void**)&sumq, g_sumq);
    cudaGetSymbolAddress((void**)&rS,   g_rS);
    cudaGetSymbolAddress((void**)&Aq,   g_Aq);
    cudaGetSymbolAddress((void**)&sumh, g_sumh);
    cudaGetSymbolAddress((void**)&rqh,  g_rqh);
    cudaGetSymbolAddress((void**)&Dh,   g_Dh);
    cudaGetSymbolAddress((void**)&hb,   g_h);

    unsigned short *whi, *wlo, *xhi, *xlo, *qhi, *qlo, *tbhi, *tblo,
                   *aqhi, *aqlo, *thhi, *thlo;
    cudaGetSymbolAddress((void**)&whi,  g_whi);
    cudaGetSymbolAddress((void**)&wlo,  g_wlo);
    cudaGetSymbolAddress((void**)&xhi,  g_xhi);
    cudaGetSymbolAddress((void**)&xlo,  g_xlo);
    cudaGetSymbolAddress((void**)&qhi,  g_qhi);
    cudaGetSymbolAddress((void**)&qlo,  g_qlo);
    cudaGetSymbolAddress((void**)&tbhi, g_tbhi);
    cudaGetSymbolAddress((void**)&tblo, g_tblo);
    cudaGetSymbolAddress((void**)&aqhi, g_Aqhi);
    cudaGetSymbolAddress((void**)&aqlo, g_Aqlo);
    cudaGetSymbolAddress((void**)&thhi, g_thhi);
    cudaGetSymbolAddress((void**)&thlo, g_thlo);

    cudaFuncSetAttribute(gemm_pc<0,0>, cudaFuncAttributeMaxDynamicSharedMemorySize, SMEM_TOTAL);
    cudaFuncSetAttribute(gemm_pc<0,1>, cudaFuncAttributeMaxDynamicSharedMemorySize, SMEM_TOTAL);
    cudaFuncSetAttribute(gemm_pc<1,0>, cudaFuncAttributeMaxDynamicSharedMemorySize, SMEM_TOTAL);
    cudaFuncSetAttribute(gemm_pc<2,0>, cudaFuncAttributeMaxDynamicSharedMemorySize, SMEM_TOTAL);
    cudaFuncSetAttribute(gemm_pc<3,1>, cudaFuncAttributeMaxDynamicSharedMemorySize, SMEM_TOTAL);

    // ---- one-time (per launch) weight & x splitting ----
    auto SPL = [&](const float* src, unsigned short* hi, unsigned short* lo, int n) {
        const int n4 = n / 4;
        k_split<<<(n4 + 255) / 256, 256>>>(src, hi, lo, n4);
    };
    SPL(W_S,    whi + O_WS,    wlo + O_WS,    NW_WS);
    SPL(W_sq,   whi + O_WSQ,   wlo + O_WSQ,   NW_WSQ);
    SPL(W_h0q,  whi + O_WH0Q,  wlo + O_WH0Q,  NW_WH0Q);
    SPL(W_h0h,  whi + O_WH0H,  wlo + O_WH0H,  NW_WH0H);
    SPL(W_q0h,  whi + O_WQ0H,  wlo + O_WQ0H,  NW_WQ0H);
    SPL(W_out,  whi + O_WOUT,  wlo + O_WOUT,  NW_WOUT);
    SPL(Wb_Aq,  whi + O_WAQ,   wlo + O_WAQ,   NW_WAQ);
    SPL(Wb_Dh,  whi + O_WDH,   wlo + O_WDH,   NW_WDH);
    SPL(Wb_fh,  whi + O_WFH,   wlo + O_WFH,   NW_WFH);
    SPL(Wb_hf,  whi + O_WHF,   wlo + O_WHF,   NW_WHF);
    SPL(Wb_resq,whi + O_WRESQ, wlo + O_WRESQ, NW_WRESQ);
    SPL(x,      xhi,           xlo,           NX);

    const dim3 gF(FDIM / BN, N_ROWS / BM);   // (16, 64)
    const dim3 gH(HDIM / BN, N_ROWS / BM);   // (8, 64)
    const int ewF = (N_ROWS * FDIM / 4) / 256;
    const int ewH = (N_ROWS * HDIM / 4) / 256;

    // ---- prologue ----
    gemm_pc<0,0><<<gF, 256, SMEM_TOTAL>>>(xhi + HDIM, xlo + HDIM, XDIM,
        whi + O_WH0Q, wlo + O_WH0Q, b_h0q, sumq, nullptr, nullptr, FDIM, B0DIM, nullptr);
    gemm_pc<2,0><<<gF, 256, SMEM_TOTAL>>>(xhi, xlo, XDIM,
        whi + O_WSQ, wlo + O_WSQ, b_sq, sumq, nullptr, nullptr, FDIM, HDIM, nullptr);
    gemm_pc<0,0><<<gH, 256, SMEM_TOTAL>>>(xhi + HDIM, xlo + HDIM, XDIM,
        whi + O_WH0H, wlo + O_WH0H, b_h0h, sumh, nullptr, nullptr, HDIM, B0DIM, nullptr);
    gemm_pc<1,0><<<gF, 256, SMEM_TOTAL>>>(xhi + HDIM + B0DIM, xlo + HDIM + B0DIM, XDIM,
        whi + O_WS, wlo + O_WS, b_S, rS, nullptr, nullptr, FDIM, FDIM, nullptr);
    k_square<<<ewF, 256>>>(x, q, qhi, qlo);
    gemm_pc<0,0><<<gH, 256, SMEM_TOTAL>>>(qhi, qlo, FDIM,
        whi + O_WQ0H, wlo + O_WQ0H, b_q0h, rqh, nullptr, nullptr, HDIM, FDIM, nullptr);

    // ---- 6 unrolled blocks ----
    for (int nb = 0; nb < NB; nb++) {
        const size_t oAq   = O_WAQ   + (size_t)nb * FDIM * FDIM;
        const size_t oDh   = O_WDH   + (size_t)nb * HDIM * FDIM;
        const size_t oFh   = O_WFH   + (size_t)nb * HDIM * FDIM;
        const size_t oHf   = O_WHF   + (size_t)nb * FDIM * HDIM;
        const size_t oResq = O_WRESQ + (size_t)nb * HDIM * FDIM;
        const float* bAq   = bb_Aq   + (size_t)nb * FDIM;
        const float* bDh   = bb_Dh   + (size_t)nb * HDIM;
        const float* bfh   = bb_fh   + (size_t)nb * HDIM;
        const float* bhf   = bb_hf   + (size_t)nb * FDIM;
        const float* bresq = bb_resq + (size_t)nb * HDIM;

        k_mul<<<ewF, 256>>>(q, rS, tbhi, tblo);
        gemm_pc<0,1><<<gF, 256, SMEM_TOTAL>>>(tbhi, tblo, FDIM,
            whi + oAq, wlo + oAq, bAq, Aq, aqhi, aqlo, FDIM, FDIM, nullptr);
        gemm_pc<1,0><<<gH, 256, SMEM_TOTAL>>>(aqhi, aqlo, FDIM,
            whi + oDh, wlo + oDh, bDh, Dh, nullptr, nullptr, HDIM, FDIM, nullptr);
        k_hid<<<ewF, 256>>>(Aq, q, sumq, tbhi, tblo);
        gemm_pc<1,0><<<gH, 256, SMEM_TOTAL>>>(tbhi, tblo, FDIM,
            whi + oFh, wlo + oFh, bfh, hb, nullptr, nullptr, HDIM, FDIM, nullptr);
        k_comb<<<ewH, 256>>>(hb, sumh, rqh, Dh, thhi, thlo);
        gemm_pc<3,1><<<gF, 256, SMEM_TOTAL>>>(thhi, thlo, HDIM,
            whi + oHf, wlo + oHf, bhf, q, qhi, qlo, FDIM, HDIM, a_hf + nb);
        gemm_pc<1,0><<<gH, 256, SMEM_TOTAL>>>(qhi, qlo, FDIM,
            whi + oResq, wlo + oResq, bresq, rqh, nullptr, nullptr, HDIM, FDIM, nullptr);
    }

    // ---- output ----
    gemm_pc<0,0><<<gF, 256, SMEM_TOTAL>>>(qhi, qlo, FDIM,
        whi + O_WOUT, wlo + O_WOUT, b_out, (float*)d_out, nullptr, nullptr, ODIM, FDIM, nullptr);
}

// round 12
// speedup vs baseline: 2.3407x; 1.5516x over previous
#include <cuda_runtime.h>
#include <cuda_fp16.h>
#include <cstdint>

// Problem constants
#define N_ROWS 8192
#define HDIM   1024
#define B0DIM  64
#define FDIM   2048
#define ODIM   2048
#define XDIM   (HDIM + B0DIM + FDIM)   // 3136
#define NB     6

#define BM 128
#define BN 128
#define BK 32

// smem: rows are exactly 64B (32 fp16); segment-XOR swizzle kills conflicts.
// swizzled byte offset of (row r, 16B-segment s): r*64 + ((s ^ ((r>>1)&3))<<4)
#define OFF_A    0
#define OFF_BHI  8192
#define OFF_BLO  16384
#define SM_STAGE 24576
#define NSTG     3
#define SMEM_TOTAL (NSTG * SM_STAGE)   // 73728 -> 2 CTAs/SM

// weight arena element offsets
#define NW_WS    (FDIM * FDIM)
#define NW_WSQ   (FDIM * HDIM)
#define NW_WH0Q  (FDIM * B0DIM)
#define NW_WH0H  (HDIM * B0DIM)
#define NW_WQ0H  (HDIM * FDIM)
#define NW_WOUT  (ODIM * FDIM)
#define NW_WAQ   (NB * FDIM * FDIM)
#define NW_WDH   (NB * HDIM * FDIM)
#define NW_WFH   (NB * HDIM * FDIM)
#define NW_WHF   (NB * FDIM * HDIM)
#define NW_WRESQ (NB * HDIM * FDIM)

#define O_WS    0
#define O_WSQ   (O_WS + NW_WS)
#define O_WH0Q  (O_WSQ + NW_WSQ)
#define O_WH0H  (O_WH0Q + NW_WH0Q)
#define O_WQ0H  (O_WH0H + NW_WH0H)
#define O_WOUT  (O_WQ0H + NW_WQ0H)
#define O_WAQ   (O_WOUT + NW_WOUT)
#define O_WDH   (O_WAQ + NW_WAQ)
#define O_WFH   (O_WDH + NW_WDH)
#define O_WHF   (O_WFH + NW_WFH)
#define O_WRESQ (O_WHF + NW_WHF)
#define NW_TOT  (O_WRESQ + NW_WRESQ)

#define NX   (N_ROWS * XDIM)
#define NF   (N_ROWS * FDIM)
#define NH   (N_ROWS * HDIM)

// -------------------- scratch (device globals; no allocs allowed) ---------
__device__ float g_q   [NF];
__device__ float g_sumq[NF];
__device__ float g_rS  [NF];
__device__ float g_Aq  [NF];
__device__ float g_sumh[NH];
__device__ float g_rqh [NH];
__device__ float g_Dh  [NH];
__device__ float g_h   [NH];

__device__ unsigned short g_whi[NW_TOT];   // weight fp16 hi plane
__device__ unsigned short g_wlo[NW_TOT];   // weight fp16 lo plane
__device__ unsigned short g_xh [NX];       // activation fp16 planes
__device__ unsigned short g_qh [NF];
__device__ unsigned short g_tbh[NF];
__device__ unsigned short g_Aqh[NF];
__device__ unsigned short g_thh[NH];

// -------------------- helpers ---------------------------------------------
__device__ __forceinline__ uint32_t swz(int row, int seg)
{
    return (uint32_t)(row * 64 + ((seg ^ ((row >> 1) & 3)) << 4));
}

__device__ __forceinline__ void ldsm_x4(uint32_t& r0, uint32_t& r1,
                                        uint32_t& r2, uint32_t& r3,
                                        uint32_t addr)
{
    asm volatile("ldmatrix.sync.aligned.m8n8.x4.shared.b16 {%0,%1,%2,%3}, [%4];"
                 : "=r"(r0), "=r"(r1), "=r"(r2), "=r"(r3) : "r"(addr));
}

__device__ __forceinline__ void mma16816(float* c, const uint32_t* a,
                                         uint32_t b0, uint32_t b1)
{
    asm volatile(
        "mma.sync.aligned.m16n8k16.row.col.f32.f16.f16.f32 "
        "{%0,%1,%2,%3}, {%4,%5,%6,%7}, {%8,%9}, {%0,%1,%2,%3};"
        : "+f"(c[0]), "+f"(c[1]), "+f"(c[2]), "+f"(c[3])
        : "r"(a[0]), "r"(a[1]), "r"(a[2]), "r"(a[3]), "r"(b0), "r"(b1));
}

// pack 2 floats to fp16x2 (activation plane)
__device__ __forceinline__ uint32_t packh2(float x, float y)
{
    __half hx = __float2half_rn(x);
    __half hy = __float2half_rn(y);
    return ((uint32_t)__half_as_ushort(hy) << 16) | __half_as_ushort(hx);
}

// weight split: fp16 hi + fp16 lo (residual)
__device__ __forceinline__ void split2(float x, float y, uint32_t& hi, uint32_t& lo)
{
    __half hx = __float2half_rn(x);
    __half hy = __float2half_rn(y);
    __half lx = __float2half_rn(x - __half2float(hx));
    __half ly = __float2half_rn(y - __half2float(hy));
    hi = ((uint32_t)__half_as_ushort(hy) << 16) | __half_as_ushort(hx);
    lo = ((uint32_t)__half_as_ushort(ly) << 16) | __half_as_ushort(lx);
}

__device__ __forceinline__ void cpa16(uint32_t dst, const void* src)
{
    asm volatile("cp.async.cg.shared.global [%0], [%1], 16;"
                 :: "r"(dst), "l"(src) : "memory");
}
#define CPA_COMMIT() asm volatile("cp.async.commit_group;" ::: "memory")
#define CPA_WAIT(n)  asm volatile("cp.async.wait_group %0;" :: "n"(n) : "memory")

// -------------------- fp16x2 tensor GEMM (3-stage pipeline) ---------------
// C = epi(A[M,K] @ W[Fout,K]^T + bias)
// A: single fp16 plane. W: fp16 hi+lo planes (2 MMA passes: A*Whi + A*Wlo).
// MODE 0: C = acc + b ; 1: relu ; 2: C += acc + b ; 3: C = C - leaky(acc+b)
// WB: also write fp16 plane of the result (Ch).
template <int MODE, int WB>
__global__ __launch_bounds__(256, 2) void gemm_pc(
    const unsigned short* __restrict__ A, int lda,
    const unsigned short* __restrict__ Whi,
    const unsigned short* __restrict__ Wlo,     // ldw == K
    const float* __restrict__ bias,
    float* __restrict__ C,
    unsigned short* __restrict__ Ch, int ldc,
    int K,
    const float* __restrict__ a_ptr)
{
    extern __shared__ __align__(16) char smem[];
    const uint32_t sb = (uint32_t)__cvta_generic_to_shared(smem);

    const int t    = threadIdx.x;
    const int lane = t & 31;
    const int warp = t >> 5;
    const int wm   = warp >> 1;      // 0..3
    const int wn   = warp & 1;       // 0..1
    const int m0   = wm * 32;        // warp tile 32x64
    const int n0   = wn * 64;
    const int brow = blockIdx.y * BM;
    const int bcol = blockIdx.x * BN;

    // copy mapping: row = t>>1, k-half = (t&1)*16 elements = segments {2h, 2h+1}
    const int crow = t >> 1;
    const int s0   = (t & 1) * 2;
    const size_t aIdx = (size_t)(brow + crow) * lda + (t & 1) * 16;
    const size_t bIdx = (size_t)(bcol + crow) * K   + (t & 1) * 16;
    const uint32_t d0 = swz(crow, s0);
    const uint32_t d1 = swz(crow, s0 + 1);

    float acc[2][8][4];
#pragma unroll
    for (int mt = 0; mt < 2; mt++)
#pragma unroll
        for (int nt = 0; nt < 8; nt++)
#pragma unroll
            for (int i = 0; i < 4; i++) acc[mt][nt][i] = 0.f;

    // per-lane ldmatrix row/segment bases
    const int rA0    = m0 + (lane & 15);
    const int sAbase = lane >> 4;                       // 0/1
    const int rB0    = n0 + (lane & 7) + ((lane >> 4) << 3);
    const int sBbase = (lane >> 3) & 1;                 // 0/1

    const int nch = K / BK;

    // issue stage 0 (chunk 0)
    {
        const uint32_t sd = sb;
        cpa16(sd + OFF_A   + d0, A   + aIdx);
        cpa16(sd + OFF_A   + d1, A   + aIdx + 8);
        cpa16(sd + OFF_BHI + d0, Whi + bIdx);
        cpa16(sd + OFF_BHI + d1, Whi + bIdx + 8);
        cpa16(sd + OFF_BLO + d0, Wlo + bIdx);
        cpa16(sd + OFF_BLO + d1, Wlo + bIdx + 8);
        CPA_COMMIT();
    }

    int stg = 0;       // stage index of chunk c
    for (int c = 0; c < nch; c++) {
        if (c + 1 < nch) {
            const int k1 = (c + 1) * BK;
            int stg1 = stg + 1; if (stg1 == NSTG) stg1 = 0;
            const uint32_t sd = sb + (uint32_t)stg1 * SM_STAGE;
            cpa16(sd + OFF_A   + d0, A   + aIdx + k1);
            cpa16(sd + OFF_A   + d1, A   + aIdx + k1 + 8);
            cpa16(sd + OFF_BHI + d0, Whi + bIdx + k1);
            cpa16(sd + OFF_BHI + d1, Whi + bIdx + k1 + 8);
            cpa16(sd + OFF_BLO + d0, Wlo + bIdx + k1);
            cpa16(sd + OFF_BLO + d1, Wlo + bIdx + k1 + 8);
            CPA_COMMIT();
            CPA_WAIT(1);
        } else {
            CPA_WAIT(0);
        }
        __syncthreads();   // single barrier per chunk (3-stage ring makes this safe)

        // ---- MMA from stage stg: pass1 A*Whi, pass2 A*Wlo (A frags reused)
        const uint32_t stgb = sb + (uint32_t)stg * SM_STAGE;
#pragma unroll
        for (int kk = 0; kk < BK; kk += 16) {
            const int sA = sAbase + (kk >> 3);
            const int sB = sBbase + (kk >> 3);
            uint32_t b[4][4];
#pragma unroll
            for (int g = 0; g < 4; g++)
                ldsm_x4(b[g][0], b[g][1], b[g][2], b[g][3],
                        stgb + OFF_BHI + swz(rB0 + g * 16, sB));
            uint32_t a[2][4];
#pragma unroll
            for (int mt = 0; mt < 2; mt++)
                ldsm_x4(a[mt][0], a[mt][1], a[mt][2], a[mt][3],
                        stgb + OFF_A + swz(rA0 + mt * 16, sA));
#pragma unroll
            for (int mt = 0; mt < 2; mt++)
#pragma unroll
                for (int nt = 0; nt < 8; nt++)
                    mma16816(acc[mt][nt], a[mt],
                             b[nt >> 1][(nt & 1) * 2], b[nt >> 1][(nt & 1) * 2 + 1]);
#pragma unroll
            for (int g = 0; g < 4; g++)
                ldsm_x4(b[g][0], b[g][1], b[g][2], b[g][3],
                        stgb + OFF_BLO + swz(rB0 + g * 16, sB));
#pragma unroll
            for (int mt = 0; mt < 2; mt++)
#pragma unroll
                for (int nt = 0; nt < 8; nt++)
                    mma16816(acc[mt][nt], a[mt],
                             b[nt >> 1][(nt & 1) * 2], b[nt >> 1][(nt & 1) * 2 + 1]);
        }
        if (++stg == NSTG) stg = 0;
    }

    // ---- epilogue ----
    const float alpha = (MODE == 3) ? a_ptr[0] : 0.f;
#pragma unroll
    for (int mt = 0; mt < 2; mt++) {
#pragma unroll
        for (int half = 0; half < 2; half++) {
            const int row = brow + m0 + mt * 16 + (lane >> 2) + half * 8;
            const int col0 = bcol + n0 + (lane & 3) * 2;
            float* Crow = C + (size_t)row * ldc + col0;
            const float* brow_b = bias + col0;
#pragma unroll
            for (int nt = 0; nt < 8; nt++) {
                float v0 = acc[mt][nt][half * 2 + 0] + brow_b[nt * 8 + 0];
                float v1 = acc[mt][nt][half * 2 + 1] + brow_b[nt * 8 + 1];
                if (MODE == 1) {
                    v0 = v0 > 0.f ? v0 : 0.f;
                    v1 = v1 > 0.f ? v1 : 0.f;
                }
                if (MODE == 2) {
                    float2 old = *(float2*)(Crow + nt * 8);
                    v0 += old.x; v1 += old.y;
                }
                if (MODE == 3) {
                    float2 old = *(float2*)(Crow + nt * 8);
                    float l0 = (v0 >= 0.f) ? v0 : alpha * v0;
                    float l1 = (v1 >= 0.f) ? v1 : alpha * v1;
                    v0 = old.x - l0; v1 = old.y - l1;
                }
                *(float2*)(Crow + nt * 8) = make_float2(v0, v1);
                if (WB) {
                    *(uint32_t*)(Ch + (size_t)row * ldc + col0 + nt * 8) =
                        packh2(v0, v1);
                }
            }
        }
    }
}

// -------------------- converters & elementwise (float4 vectorized) --------
// weight split: fp16 hi + lo
__global__ __launch_bounds__(256) void k_split(const float* __restrict__ in,
                                               unsigned short* __restrict__ hi,
                                               unsigned short* __restrict__ lo,
                                               int n4)
{
    const int i = blockIdx.x * blockDim.x + threadIdx.x;
    if (i >= n4) return;
    float4 v = ((const float4*)in)[i];
    uint32_t h0, l0, h1, l1;
    split2(v.x, v.y, h0, l0);
    split2(v.z, v.w, h1, l1);
    ((uint2*)hi)[i] = make_uint2(h0, h1);
    ((uint2*)lo)[i] = make_uint2(l0, l1);
}

// activation convert: fp16 plane only
__global__ __launch_bounds__(256) void k_cvt(const float* __restrict__ in,
                                             unsigned short* __restrict__ h,
                                             int n4)
{
    const int i = blockIdx.x * blockDim.x + threadIdx.x;
    if (i >= n4) return;
    float4 v = ((const float4*)in)[i];
    ((uint2*)h)[i] = make_uint2(packh2(v.x, v.y), packh2(v.z, v.w));
}

// q = (pi/4)*d^2 ; writes fp32 + fp16 plane
__global__ __launch_bounds__(256) void k_square(const float* __restrict__ x,
                                                float* __restrict__ q,
                                                unsigned short* __restrict__ qh)
{
    const int i = blockIdx.x * blockDim.x + threadIdx.x;
    const int row = i / (FDIM / 4);
    const int c4  = i % (FDIM / 4);
    const float4 d = *(const float4*)(x + (size_t)row * XDIM + HDIM + B0DIM + c4 * 4);
    const float s = 0.78539816339744830962f;
    float4 o;
    o.x = s * d.x * d.x; o.y = s * d.y * d.y;
    o.z = s * d.z * d.z; o.w = s * d.w * d.w;
    const int oi = row * (FDIM / 4) + c4;
    ((float4*)q)[oi] = o;
    ((uint2*)qh)[oi] = make_uint2(packh2(o.x, o.y), packh2(o.z, o.w));
}

// tbh = fp16(q * rS)
__global__ __launch_bounds__(256) void k_mul(const float* __restrict__ a,
                                             const float* __restrict__ b,
                                             unsigned short* __restrict__ oh)
{
    const int i = blockIdx.x * blockDim.x + threadIdx.x;
    const float4 av = ((const float4*)a)[i];
    const float4 bv = ((const float4*)b)[i];
    float4 o;
    o.x = av.x * bv.x; o.y = av.y * bv.y;
    o.z = av.z * bv.z; o.w = av.w * bv.w;
    ((uint2*)oh)[i] = make_uint2(packh2(o.x, o.y), packh2(o.z, o.w));
}

// tbh = fp16(Aq * (q + sumq))
__global__ __launch_bounds__(256) void k_hid(const float* __restrict__ Aq,
                                             const float* __restrict__ q,
                                             const float* __restrict__ sumq,
                                             unsigned short* __restrict__ oh)
{
    const int i = blockIdx.x * blockDim.x + threadIdx.x;
    const float4 a = ((const float4*)Aq)[i];
    const float4 b = ((const float4*)q)[i];
    const float4 c = ((const float4*)sumq)[i];
    float4 o;
    o.x = a.x * (b.x + c.x); o.y = a.y * (b.y + c.y);
    o.z = a.z * (b.z + c.z); o.w = a.w * (b.w + c.w);
    ((uint2*)oh)[i] = make_uint2(packh2(o.x, o.y), packh2(o.z, o.w));
}

// thh = fp16((h + sumh + rqh) * Dh)
__global__ __launch_bounds__(256) void k_comb(const float* __restrict__ h,
                                              const float* __restrict__ sumh,
                                              const float* __restrict__ rqh,
                                              const float* __restrict__ Dh,
                                              unsigned short* __restrict__ oh)
{
    const int i = blockIdx.x * blockDim.x + threadIdx.x;
    const float4 a = ((const float4*)h)[i];
    const float4 b = ((const float4*)sumh)[i];
    const float4 c = ((const float4*)rqh)[i];
    const float4 d = ((const float4*)Dh)[i];
    float4 o;
    o.x = (a.x + b.x + c.x) * d.x; o.y = (a.y + b.y + c.y) * d.y;
    o.z = (a.z + b.z + c.z) * d.z; o.w = (a.w + b.w + c.w) * d.w;
    ((uint2*)oh)[i] = make_uint2(packh2(o.x, o.y), packh2(o.z, o.w));
}

// -------------------- driver ----------------------------------------------
extern "C" void kernel_launch(void* const* d_in, const int* in_sizes, int n_in,
                              void* d_out, int out_size)
{
    const float* x      = (const float*)d_in[0];
    const float* W_h0q  = (const float*)d_in[1];
    const float* b_h0q  = (const float*)d_in[2];
    const float* W_sq   = (const float*)d_in[3];
    const float* b_sq   = (const float*)d_in[4];
    const float* W_h0h  = (const float*)d_in[5];
    const float* b_h0h  = (const float*)d_in[6];
    const float* W_S    = (const float*)d_in[7];
    const float* b_S    = (const float*)d_in[8];
    const float* W_q0h  = (const float*)d_in[9];
    const float* b_q0h  = (const float*)d_in[10];
    const float* Wb_Aq  = (const float*)d_in[11];
    const float* bb_Aq  = (const float*)d_in[12];
    const float* Wb_Dh  = (const float*)d_in[13];
    const float* bb_Dh  = (const float*)d_in[14];
    const float* Wb_fh  = (const float*)d_in[15];
    const float* bb_fh  = (const float*)d_in[16];
    const float* Wb_hf  = (const float*)d_in[17];
    const float* bb_hf  = (const float*)d_in[18];
    const float* a_hf   = (const float*)d_in[19];
    const float* Wb_resq= (const float*)d_in[20];
    const float* bb_resq= (const float*)d_in[21];
    const float* W_out  = (const float*)d_in[22];
    const float* b_out  = (const float*)d_in[23];

    float *q, *sumq, *rS, *Aq, *sumh, *rqh, *Dh, *hb;
    cudaGetSymbolAddress((void**)&q,    g_q);
    cudaGetSymbolAddress((void**)&sumq, g_sumq);
    cudaGetSymbolAddress((void**)&rS,   g_rS);
    cudaGetSymbolAddress((void**)&Aq,   g_Aq);
    cudaGetSymbolAddress((void**)&sumh, g_sumh);
    cudaGetSymbolAddress((void**)&rqh,  g_rqh);
    cudaGetSymbolAddress((void**)&Dh,   g_Dh);
    cudaGetSymbolAddress((void**)&hb,   g_h);

    unsigned short *whi, *wlo, *xh, *qh, *tbh, *aqh, *thh;
    cudaGetSymbolAddress((void**)&whi, g_whi);
    cudaGetSymbolAddress((void**)&wlo, g_wlo);
    cudaGetSymbolAddress((void**)&xh,  g_xh);
    cudaGetSymbolAddress((void**)&qh,  g_qh);
    cudaGetSymbolAddress((void**)&tbh, g_tbh);
    cudaGetSymbolAddress((void**)&aqh, g_Aqh);
    cudaGetSymbolAddress((void**)&thh, g_thh);

    cudaFuncSetAttribute(gemm_pc<0,0>, cudaFuncAttributeMaxDynamicSharedMemorySize, SMEM_TOTAL);
    cudaFuncSetAttribute(gemm_pc<0,1>, cudaFuncAttributeMaxDynamicSharedMemorySize, SMEM_TOTAL);
    cudaFuncSetAttribute(gemm_pc<1,0>, cudaFuncAttributeMaxDynamicSharedMemorySize, SMEM_TOTAL);
    cudaFuncSetAttribute(gemm_pc<2,0>, cudaFuncAttributeMaxDynamicSharedMemorySize, SMEM_TOTAL);
    cudaFuncSetAttribute(gemm_pc<3,1>, cudaFuncAttributeMaxDynamicSharedMemorySize, SMEM_TOTAL);

    // ---- one-time (per launch) weight splitting + x conversion ----
    auto SPL = [&](const float* src, unsigned short* hi, unsigned short* lo, int n) {
        const int n4 = n / 4;
        k_split<<<(n4 + 255) / 256, 256>>>(src, hi, lo, n4);
    };
    SPL(W_S,    whi + O_WS,    wlo + O_WS,    NW_WS);
    SPL(W_sq,   whi + O_WSQ,   wlo + O_WSQ,   NW_WSQ);
    SPL(W_h0q,  whi + O_WH0Q,  wlo + O_WH0Q,  NW_WH0Q);
    SPL(W_h0h,  whi + O_WH0H,  wlo + O_WH0H,  NW_WH0H);
    SPL(W_q0h,  whi + O_WQ0H,  wlo + O_WQ0H,  NW_WQ0H);
    SPL(W_out,  whi + O_WOUT,  wlo + O_WOUT,  NW_WOUT);
    SPL(Wb_Aq,  whi + O_WAQ,   wlo + O_WAQ,   NW_WAQ);
    SPL(Wb_Dh,  whi + O_WDH,   wlo + O_WDH,   NW_WDH);
    SPL(Wb_fh,  whi + O_WFH,   wlo + O_WFH,   NW_WFH);
    SPL(Wb_hf,  whi + O_WHF,   wlo + O_WHF,   NW_WHF);
    SPL(Wb_resq,whi + O_WRESQ, wlo + O_WRESQ, NW_WRESQ);
    k_cvt<<<(NX / 4 + 255) / 256, 256>>>(x, xh, NX / 4);

    const dim3 gF(FDIM / BN, N_ROWS / BM);   // (16, 64)
    const dim3 gH(HDIM / BN, N_ROWS / BM);   // (8, 64)
    const int ewF = (N_ROWS * FDIM / 4) / 256;
    const int ewH = (N_ROWS * HDIM / 4) / 256;

    // ---- prologue ----
    gemm_pc<0,0><<<gF, 256, SMEM_TOTAL>>>(xh + HDIM, XDIM,
        whi + O_WH0Q, wlo + O_WH0Q, b_h0q, sumq, nullptr, FDIM, B0DIM, nullptr);
    gemm_pc<2,0><<<gF, 256, SMEM_TOTAL>>>(xh, XDIM,
        whi + O_WSQ, wlo + O_WSQ, b_sq, sumq, nullptr, FDIM, HDIM, nullptr);
    gemm_pc<0,0><<<gH, 256, SMEM_TOTAL>>>(xh + HDIM, XDIM,
        whi + O_WH0H, wlo + O_WH0H, b_h0h, sumh, nullptr, HDIM, B0DIM, nullptr);
    gemm_pc<1,0><<<gF, 256, SMEM_TOTAL>>>(xh + HDIM + B0DIM, XDIM,
        whi + O_WS, wlo + O_WS, b_S, rS, nullptr, FDIM, FDIM, nullptr);
    k_square<<<ewF, 256>>>(x, q, qh);
    gemm_pc<0,0><<<gH, 256, SMEM_TOTAL>>>(qh, FDIM,
        whi + O_WQ0H, wlo + O_WQ0H, b_q0h, rqh, nullptr, HDIM, FDIM, nullptr);

    // ---- 6 unrolled blocks ----
    for (int nb = 0; nb < NB; nb++) {
        const size_t oAq   = O_WAQ   + (size_t)nb * FDIM * FDIM;
        const size_t oDh   = O_WDH   + (size_t)nb * HDIM * FDIM;
        const size_t oFh   = O_WFH   + (size_t)nb * HDIM * FDIM;
        const size_t oHf   = O_WHF   + (size_t)nb * FDIM * HDIM;
        const size_t oResq = O_WRESQ + (size_t)nb * HDIM * FDIM;
        const float* bAq   = bb_Aq   + (size_t)nb * FDIM;
        const float* bDh   = bb_Dh   + (size_t)nb * HDIM;
        const float* bfh   = bb_fh   + (size_t)nb * HDIM;
        const float* bhf   = bb_hf   + (size_t)nb * FDIM;
        const float* bresq = bb_resq + (size_t)nb * HDIM;

        k_mul<<<ewF, 256>>>(q, rS, tbh);
        gemm_pc<0,1><<<gF, 256, SMEM_TOTAL>>>(tbh, FDIM,
            whi + oAq, wlo + oAq, bAq, Aq, aqh, FDIM, FDIM, nullptr);
        gemm_pc<1,0><<<gH, 256, SMEM_TOTAL>>>(aqh, FDIM,
            whi + oDh, wlo + oDh, bDh, Dh, nullptr, HDIM, FDIM, nullptr);
        k_hid<<<ewF, 256>>>(Aq, q, sumq, tbh);
        gemm_pc<1,0><<<gH, 256, SMEM_TOTAL>>>(tbh, FDIM,
            whi + oFh, wlo + oFh, bfh, hb, nullptr, HDIM, FDIM, nullptr);
        k_comb<<<ewH, 256>>>(hb, sumh, rqh, Dh, thh);
        gemm_pc<3,1><<<gF, 256, SMEM_TOTAL>>>(thh, HDIM,
            whi + oHf, wlo + oHf, bhf, q, qh, FDIM, HDIM, a_hf + nb);
        gemm_pc<1,0><<<gH, 256, SMEM_TOTAL>>>(qh, FDIM,
            whi + oResq, wlo + oResq, bresq, rqh, nullptr, HDIM, FDIM, nullptr);
    }

    // ---- output ----
    gemm_pc<0,0><<<gF, 256, SMEM_TOTAL>>>(qh, FDIM,
        whi + O_WOUT, wlo + O_WOUT, b_out, (float*)d_out, nullptr, ODIM, FDIM, nullptr);
}

// round 13
// speedup vs baseline: 3.6787x; 1.5716x over previous
#include <cuda_runtime.h>
#include <cuda_fp16.h>
#include <cstdint>

// Problem constants
#define N_ROWS 8192
#define HDIM   1024
#define B0DIM  64
#define FDIM   2048
#define ODIM   2048
#define XDIM   (HDIM + B0DIM + FDIM)   // 3136
#define NB     6

#define BM 128
#define BN 128
#define BK 32

// smem: rows are exactly 64B (32 fp16); segment-XOR swizzle kills conflicts.
#define OFF_A    0
#define OFF_B    8192
#define SM_STAGE 16384
#define NSTG     4
#define SMEM_TOTAL (NSTG * SM_STAGE)   // 65536 -> 2 CTAs/SM

// weight arena element offsets (single fp16 plane)
#define NW_WS    (FDIM * FDIM)
#define NW_WSQ   (FDIM * HDIM)
#define NW_WH0Q  (FDIM * B0DIM)
#define NW_WH0H  (HDIM * B0DIM)
#define NW_WQ0H  (HDIM * FDIM)
#define NW_WOUT  (ODIM * FDIM)
#define NW_WAQ   (NB * FDIM * FDIM)
#define NW_WDH   (NB * HDIM * FDIM)
#define NW_WFH   (NB * HDIM * FDIM)
#define NW_WHF   (NB * FDIM * HDIM)
#define NW_WRESQ (NB * HDIM * FDIM)

#define O_WS    0
#define O_WSQ   (O_WS + NW_WS)
#define O_WH0Q  (O_WSQ + NW_WSQ)
#define O_WH0H  (O_WH0Q + NW_WH0Q)
#define O_WQ0H  (O_WH0H + NW_WH0H)
#define O_WOUT  (O_WQ0H + NW_WQ0H)
#define O_WAQ   (O_WOUT + NW_WOUT)
#define O_WDH   (O_WAQ + NW_WAQ)
#define O_WFH   (O_WDH + NW_WDH)
#define O_WHF   (O_WFH + NW_WFH)
#define O_WRESQ (O_WHF + NW_WHF)
#define NW_TOT  (O_WRESQ + NW_WRESQ)

#define NX   (N_ROWS * XDIM)
#define NF   (N_ROWS * FDIM)
#define NH   (N_ROWS * HDIM)

// -------------------- scratch (device globals; no allocs allowed) ---------
__device__ float g_q   [NF];
__device__ float g_sumq[NF];
__device__ float g_rS  [NF];
__device__ float g_sumh[NH];
__device__ float g_rqh [NH];
__device__ float g_Dh  [NH];

__device__ unsigned short g_wh [NW_TOT];   // weights, fp16
__device__ unsigned short g_xh [NX];       // activations, fp16
__device__ unsigned short g_qh [NF];
__device__ unsigned short g_tbh[NF];       // A-operand of Aq GEMM
__device__ unsigned short g_tb2h[NF];      // A-operand of fh GEMM (ping-pong)
__device__ unsigned short g_aqh[NF];
__device__ unsigned short g_thh[NH];

// -------------------- helpers ---------------------------------------------
__device__ __forceinline__ uint32_t swz(int row, int seg)
{
    return (uint32_t)(row * 64 + ((seg ^ ((row >> 1) & 3)) << 4));
}

__device__ __forceinline__ void ldsm_x4(uint32_t& r0, uint32_t& r1,
                                        uint32_t& r2, uint32_t& r3,
                                        uint32_t addr)
{
    asm volatile("ldmatrix.sync.aligned.m8n8.x4.shared.b16 {%0,%1,%2,%3}, [%4];"
                 : "=r"(r0), "=r"(r1), "=r"(r2), "=r"(r3) : "r"(addr));
}

__device__ __forceinline__ void mma16816(float* c, const uint32_t* a,
                                         uint32_t b0, uint32_t b1)
{
    asm volatile(
        "mma.sync.aligned.m16n8k16.row.col.f32.f16.f16.f32 "
        "{%0,%1,%2,%3}, {%4,%5,%6,%7}, {%8,%9}, {%0,%1,%2,%3};"
        : "+f"(c[0]), "+f"(c[1]), "+f"(c[2]), "+f"(c[3])
        : "r"(a[0]), "r"(a[1]), "r"(a[2]), "r"(a[3]), "r"(b0), "r"(b1));
}

__device__ __forceinline__ uint32_t packh2(float x, float y)
{
    __half hx = __float2half_rn(x);
    __half hy = __float2half_rn(y);
    return ((uint32_t)__half_as_ushort(hy) << 16) | __half_as_ushort(hx);
}

__device__ __forceinline__ void cpa16(uint32_t dst, const void* src)
{
    asm volatile("cp.async.cg.shared.global [%0], [%1], 16;"
                 :: "r"(dst), "l"(src) : "memory");
}
#define CPA_COMMIT() asm volatile("cp.async.commit_group;" ::: "memory")
#define CPA_WAIT(n)  asm volatile("cp.async.wait_group %0;" :: "n"(n) : "memory")

// -------------------- fp16 single-pass tensor GEMM (4-stage pipeline) -----
// v = A[M,K] @ W[Fout,K]^T + bias  (A, W both single fp16 planes)
// EPI 0: C = v
// EPI 1: C = relu(v)
// EPI 2: C += v
// EPI 3: q-update: q = C - leaky(v, a); C = q; Ch = fp16(q); Xh = fp16(q*P1)
// EPI 4: Ch = fp16(v); Xh = fp16(v*(P1+P2))            (no fp32 C write)
// EPI 5: h = relu(v); Xh = fp16((h+P1+P2)*P3)          (no fp32 C write)
template <int EPI>
__global__ __launch_bounds__(256, 2) void gemm_f16(
    const unsigned short* __restrict__ A, int lda,
    const unsigned short* __restrict__ W,        // ldw == K
    const float* __restrict__ bias,
    float* __restrict__ C,
    unsigned short* __restrict__ Ch,
    unsigned short* __restrict__ Xh, int ldc,
    int K,
    const float* __restrict__ P1,
    const float* __restrict__ P2,
    const float* __restrict__ P3,
    const float* __restrict__ a_ptr)
{
    extern __shared__ __align__(16) char smem[];
    const uint32_t sb = (uint32_t)__cvta_generic_to_shared(smem);

    const int t    = threadIdx.x;
    const int lane = t & 31;
    const int warp = t >> 5;
    const int wm   = warp >> 1;      // 0..3
    const int wn   = warp & 1;       // 0..1
    const int m0   = wm * 32;        // warp tile 32x64
    const int n0   = wn * 64;
    const int brow = blockIdx.y * BM;
    const int bcol = blockIdx.x * BN;

    // copy mapping: row = t>>1, k-half = (t&1)*16 elements = segments {2h, 2h+1}
    const int crow = t >> 1;
    const int s0   = (t & 1) * 2;
    const size_t aIdx = (size_t)(brow + crow) * lda + (t & 1) * 16;
    const size_t bIdx = (size_t)(bcol + crow) * K   + (t & 1) * 16;
    const uint32_t d0 = swz(crow, s0);
    const uint32_t d1 = swz(crow, s0 + 1);

    float acc[2][8][4];
#pragma unroll
    for (int mt = 0; mt < 2; mt++)
#pragma unroll
        for (int nt = 0; nt < 8; nt++)
#pragma unroll
            for (int i = 0; i < 4; i++) acc[mt][nt][i] = 0.f;

    const int rA0    = m0 + (lane & 15);
    const int sAbase = lane >> 4;
    const int rB0    = n0 + (lane & 7) + ((lane >> 4) << 3);
    const int sBbase = (lane >> 3) & 1;

    const int nch = K / BK;

    // issue stage 0 (chunk 0)
    {
        cpa16(sb + OFF_A + d0, A + aIdx);
        cpa16(sb + OFF_A + d1, A + aIdx + 8);
        cpa16(sb + OFF_B + d0, W + bIdx);
        cpa16(sb + OFF_B + d1, W + bIdx + 8);
        CPA_COMMIT();
    }

    int stg = 0;
    for (int c = 0; c < nch; c++) {
        if (c + 1 < nch) {
            const int k1 = (c + 1) * BK;
            int stg1 = stg + 1; if (stg1 == NSTG) stg1 = 0;
            const uint32_t sd = sb + (uint32_t)stg1 * SM_STAGE;
            cpa16(sd + OFF_A + d0, A + aIdx + k1);
            cpa16(sd + OFF_A + d1, A + aIdx + k1 + 8);
            cpa16(sd + OFF_B + d0, W + bIdx + k1);
            cpa16(sd + OFF_B + d1, W + bIdx + k1 + 8);
            CPA_COMMIT();
            CPA_WAIT(1);
        } else {
            CPA_WAIT(0);
        }
        __syncthreads();   // single barrier per chunk (ring depth >= 3)

        const uint32_t stgb = sb + (uint32_t)stg * SM_STAGE;
#pragma unroll
        for (int kk = 0; kk < BK; kk += 16) {
            const int sA = sAbase + (kk >> 3);
            const int sB = sBbase + (kk >> 3);
            uint32_t b[4][4];
#pragma unroll
            for (int g = 0; g < 4; g++)
                ldsm_x4(b[g][0], b[g][1], b[g][2], b[g][3],
                        stgb + OFF_B + swz(rB0 + g * 16, sB));
            uint32_t a[2][4];
#pragma unroll
            for (int mt = 0; mt < 2; mt++)
                ldsm_x4(a[mt][0], a[mt][1], a[mt][2], a[mt][3],
                        stgb + OFF_A + swz(rA0 + mt * 16, sA));
#pragma unroll
            for (int mt = 0; mt < 2; mt++)
#pragma unroll
                for (int nt = 0; nt < 8; nt++)
                    mma16816(acc[mt][nt], a[mt],
                             b[nt >> 1][(nt & 1) * 2], b[nt >> 1][(nt & 1) * 2 + 1]);
        }
        if (++stg == NSTG) stg = 0;
    }

    // ---- epilogue ----
    const float alpha = (EPI == 3) ? a_ptr[0] : 0.f;
#pragma unroll
    for (int mt = 0; mt < 2; mt++) {
#pragma unroll
        for (int half = 0; half < 2; half++) {
            const int row  = brow + m0 + mt * 16 + (lane >> 2) + half * 8;
            const int col0 = bcol + n0 + (lane & 3) * 2;
            const size_t base = (size_t)row * ldc + col0;
            const float* brow_b = bias + col0;
#pragma unroll
            for (int nt = 0; nt < 8; nt++) {
                float v0 = acc[mt][nt][half * 2 + 0] + brow_b[nt * 8 + 0];
                float v1 = acc[mt][nt][half * 2 + 1] + brow_b[nt * 8 + 1];
                const size_t idx = base + nt * 8;
                if (EPI == 0) {
                    *(float2*)(C + idx) = make_float2(v0, v1);
                }
                if (EPI == 1) {
                    v0 = fmaxf(v0, 0.f); v1 = fmaxf(v1, 0.f);
                    *(float2*)(C + idx) = make_float2(v0, v1);
                }
                if (EPI == 2) {
                    float2 old = *(float2*)(C + idx);
                    *(float2*)(C + idx) = make_float2(old.x + v0, old.y + v1);
                }
                if (EPI == 3) {
                    float2 old = *(float2*)(C + idx);
                    float l0 = (v0 >= 0.f) ? v0 : alpha * v0;
                    float l1 = (v1 >= 0.f) ? v1 : alpha * v1;
                    float q0 = old.x - l0, q1 = old.y - l1;
                    *(float2*)(C + idx) = make_float2(q0, q1);
                    *(uint32_t*)(Ch + idx) = packh2(q0, q1);
                    float2 p1 = *(const float2*)(P1 + idx);
                    *(uint32_t*)(Xh + idx) = packh2(q0 * p1.x, q1 * p1.y);
                }
                if (EPI == 4) {
                    *(uint32_t*)(Ch + idx) = packh2(v0, v1);
                    float2 p1 = *(const float2*)(P1 + idx);
                    float2 p2 = *(const float2*)(P2 + idx);
                    *(uint32_t*)(Xh + idx) =
                        packh2(v0 * (p1.x + p2.x), v1 * (p1.y + p2.y));
                }
                if (EPI == 5) {
                    float h0 = fmaxf(v0, 0.f), h1 = fmaxf(v1, 0.f);
                    float2 p1 = *(const float2*)(P1 + idx);
                    float2 p2 = *(const float2*)(P2 + idx);
                    float2 p3 = *(const float2*)(P3 + idx);
                    *(uint32_t*)(Xh + idx) =
                        packh2((h0 + p1.x + p2.x) * p3.x,
                               (h1 + p1.y + p2.y) * p3.y);
                }
            }
        }
    }
}

// -------------------- converters & elementwise ----------------------------
__global__ __launch_bounds__(256) void k_cvt(const float* __restrict__ in,
                                             unsigned short* __restrict__ h,
                                             int n4)
{
    const int i = blockIdx.x * blockDim.x + threadIdx.x;
    if (i >= n4) return;
    float4 v = ((const float4*)in)[i];
    ((uint2*)h)[i] = make_uint2(packh2(v.x, v.y), packh2(v.z, v.w));
}

// q = (pi/4)*d^2 ; writes q fp32, qh fp16, tbh = fp16(q*rS)
__global__ __launch_bounds__(256) void k_square(const float* __restrict__ x,
                                                const float* __restrict__ rS,
                                                float* __restrict__ q,
                                                unsigned short* __restrict__ qh,
                                                unsigned short* __restrict__ tbh)
{
    const int i = blockIdx.x * blockDim.x + threadIdx.x;
    const int row = i / (FDIM / 4);
    const int c4  = i % (FDIM / 4);
    const float4 d = *(const float4*)(x + (size_t)row * XDIM + HDIM + B0DIM + c4 * 4);
    const float s = 0.78539816339744830962f;
    float4 o;
    o.x = s * d.x * d.x; o.y = s * d.y * d.y;
    o.z = s * d.z * d.z; o.w = s * d.w * d.w;
    const int oi = row * (FDIM / 4) + c4;
    ((float4*)q)[oi] = o;
    ((uint2*)qh)[oi] = make_uint2(packh2(o.x, o.y), packh2(o.z, o.w));
    const float4 r = ((const float4*)rS)[oi];
    ((uint2*)tbh)[oi] = make_uint2(packh2(o.x * r.x, o.y * r.y),
                                   packh2(o.z * r.z, o.w * r.w));
}

// -------------------- driver ----------------------------------------------
extern "C" void kernel_launch(void* const* d_in, const int* in_sizes, int n_in,
                              void* d_out, int out_size)
{
    const float* x      = (const float*)d_in[0];
    const float* W_h0q  = (const float*)d_in[1];
    const float* b_h0q  = (const float*)d_in[2];
    const float* W_sq   = (const float*)d_in[3];
    const float* b_sq   = (const float*)d_in[4];
    const float* W_h0h  = (const float*)d_in[5];
    const float* b_h0h  = (const float*)d_in[6];
    const float* W_S    = (const float*)d_in[7];
    const float* b_S    = (const float*)d_in[8];
    const float* W_q0h  = (const float*)d_in[9];
    const float* b_q0h  = (const float*)d_in[10];
    const float* Wb_Aq  = (const float*)d_in[11];
    const float* bb_Aq  = (const float*)d_in[12];
    const float* Wb_Dh  = (const float*)d_in[13];
    const float* bb_Dh  = (const float*)d_in[14];
    const float* Wb_fh  = (const float*)d_in[15];
    const float* bb_fh  = (const float*)d_in[16];
    const float* Wb_hf  = (const float*)d_in[17];
    const float* bb_hf  = (const float*)d_in[18];
    const float* a_hf   = (const float*)d_in[19];
    const float* Wb_resq= (const float*)d_in[20];
    const float* bb_resq= (const float*)d_in[21];
    const float* W_out  = (const float*)d_in[22];
    const float* b_out  = (const float*)d_in[23];

    float *q, *sumq, *rS, *sumh, *rqh, *Dh;
    cudaGetSymbolAddress((void**)&q,    g_q);
    cudaGetSymbolAddress((void**)&sumq, g_sumq);
    cudaGetSymbolAddress((void**)&rS,   g_rS);
    cudaGetSymbolAddress((void**)&sumh, g_sumh);
    cudaGetSymbolAddress((void**)&rqh,  g_rqh);
    cudaGetSymbolAddress((void**)&Dh,   g_Dh);

    unsigned short *wh, *xh, *qh, *tbh, *tb2h, *aqh, *thh;
    cudaGetSymbolAddress((void**)&wh,   g_wh);
    cudaGetSymbolAddress((void**)&xh,   g_xh);
    cudaGetSymbolAddress((void**)&qh,   g_qh);
    cudaGetSymbolAddress((void**)&tbh,  g_tbh);
    cudaGetSymbolAddress((void**)&tb2h, g_tb2h);
    cudaGetSymbolAddress((void**)&aqh,  g_aqh);
    cudaGetSymbolAddress((void**)&thh,  g_thh);

    cudaFuncSetAttribute(gemm_f16<0>, cudaFuncAttributeMaxDynamicSharedMemorySize, SMEM_TOTAL);
    cudaFuncSetAttribute(gemm_f16<1>, cudaFuncAttributeMaxDynamicSharedMemorySize, SMEM_TOTAL);
    cudaFuncSetAttribute(gemm_f16<2>, cudaFuncAttributeMaxDynamicSharedMemorySize, SMEM_TOTAL);
    cudaFuncSetAttribute(gemm_f16<3>, cudaFuncAttributeMaxDynamicSharedMemorySize, SMEM_TOTAL);
    cudaFuncSetAttribute(gemm_f16<4>, cudaFuncAttributeMaxDynamicSharedMemorySize, SMEM_TOTAL);
    cudaFuncSetAttribute(gemm_f16<5>, cudaFuncAttributeMaxDynamicSharedMemorySize, SMEM_TOTAL);

    // ---- one-time weight + x conversion to fp16 ----
    auto CVT = [&](const float* src, unsigned short* dst, int n) {
        const int n4 = n / 4;
        k_cvt<<<(n4 + 255) / 256, 256>>>(src, dst, n4);
    };
    CVT(W_S,    wh + O_WS,    NW_WS);
    CVT(W_sq,   wh + O_WSQ,   NW_WSQ);
    CVT(W_h0q,  wh + O_WH0Q,  NW_WH0Q);
    CVT(W_h0h,  wh + O_WH0H,  NW_WH0H);
    CVT(W_q0h,  wh + O_WQ0H,  NW_WQ0H);
    CVT(W_out,  wh + O_WOUT,  NW_WOUT);
    CVT(Wb_Aq,  wh + O_WAQ,   NW_WAQ);
    CVT(Wb_Dh,  wh + O_WDH,   NW_WDH);
    CVT(Wb_fh,  wh + O_WFH,   NW_WFH);
    CVT(Wb_hf,  wh + O_WHF,   NW_WHF);
    CVT(Wb_resq,wh + O_WRESQ, NW_WRESQ);
    CVT(x,      xh,           NX);

    const dim3 gF(FDIM / BN, N_ROWS / BM);   // (16, 64)
    const dim3 gH(HDIM / BN, N_ROWS / BM);   // (8, 64)
    const int ewF = (N_ROWS * FDIM / 4) / 256;

    // ---- prologue ----
    // sum_q_const = h0@W_h0q^T + b  +  s@W_sq^T + b
    gemm_f16<0><<<gF, 256, SMEM_TOTAL>>>(xh + HDIM, XDIM, wh + O_WH0Q, b_h0q,
        sumq, nullptr, nullptr, FDIM, B0DIM, nullptr, nullptr, nullptr, nullptr);
    gemm_f16<2><<<gF, 256, SMEM_TOTAL>>>(xh, XDIM, wh + O_WSQ, b_sq,
        sumq, nullptr, nullptr, FDIM, HDIM, nullptr, nullptr, nullptr, nullptr);
    // sum_h_const
    gemm_f16<0><<<gH, 256, SMEM_TOTAL>>>(xh + HDIM, XDIM, wh + O_WH0H, b_h0h,
        sumh, nullptr, nullptr, HDIM, B0DIM, nullptr, nullptr, nullptr, nullptr);
    // res_S_q = relu(d@W_S^T + b)
    gemm_f16<1><<<gF, 256, SMEM_TOTAL>>>(xh + HDIM + B0DIM, XDIM, wh + O_WS, b_S,
        rS, nullptr, nullptr, FDIM, FDIM, nullptr, nullptr, nullptr, nullptr);
    // q = pi/4 d^2 ; qh ; tbh = fp16(q*rS)
    k_square<<<ewF, 256>>>(x, rS, q, qh, tbh);
    // res_q_h = q@W_q0h^T + b   (no relu in prologue)
    gemm_f16<0><<<gH, 256, SMEM_TOTAL>>>(qh, FDIM, wh + O_WQ0H, b_q0h,
        rqh, nullptr, nullptr, HDIM, FDIM, nullptr, nullptr, nullptr, nullptr);

    // ---- 6 unrolled blocks (5 GEMMs each, all elementwise fused) ----
    for (int nb = 0; nb < NB; nb++) {
        const size_t oAq   = O_WAQ   + (size_t)nb * FDIM * FDIM;
        const size_t oDh   = O_WDH   + (size_t)nb * HDIM * FDIM;
        const size_t oFh   = O_WFH   + (size_t)nb * HDIM * FDIM;
        const size_t oHf   = O_WHF   + (size_t)nb * FDIM * HDIM;
        const size_t oResq = O_WRESQ + (size_t)nb * HDIM * FDIM;
        const float* bAq   = bb_Aq   + (size_t)nb * FDIM;
        const float* bDh   = bb_Dh   + (size_t)nb * HDIM;
        const float* bfh   = bb_fh   + (size_t)nb * HDIM;
        const float* bhf   = bb_hf   + (size_t)nb * FDIM;
        const float* bresq = bb_resq + (size_t)nb * HDIM;

        // A_q = tbh @ W_Aq^T + b ; aqh = fp16(A_q) ; tb2h = fp16(A_q*(q+sumq))
        gemm_f16<4><<<gF, 256, SMEM_TOTAL>>>(tbh, FDIM, wh + oAq, bAq,
            nullptr, aqh, tb2h, FDIM, FDIM, q, sumq, nullptr, nullptr);
        // D_h = relu(aqh @ W_Dh^T + b)
        gemm_f16<1><<<gH, 256, SMEM_TOTAL>>>(aqh, FDIM, wh + oDh, bDh,
            Dh, nullptr, nullptr, HDIM, FDIM, nullptr, nullptr, nullptr, nullptr);
        // h = relu(tb2h @ W_fh^T + b) ; thh = fp16((h+sumh+rqh)*Dh)
        gemm_f16<5><<<gH, 256, SMEM_TOTAL>>>(tb2h, FDIM, wh + oFh, bfh,
            nullptr, nullptr, thh, HDIM, FDIM, sumh, rqh, Dh, nullptr);
        // q = q - leaky(thh @ W_hf^T + b) ; qh ; tbh = fp16(q*rS)
        gemm_f16<3><<<gF, 256, SMEM_TOTAL>>>(thh, HDIM, wh + oHf, bhf,
            q, qh, tbh, FDIM, HDIM, rS, nullptr, nullptr, a_hf + nb);
        // res_q_h = relu(qh @ W_resq^T + b)
        gemm_f16<1><<<gH, 256, SMEM_TOTAL>>>(qh, FDIM, wh + oResq, bresq,
            rqh, nullptr, nullptr, HDIM, FDIM, nullptr, nullptr, nullptr, nullptr);
    }

    // ---- output ----
    gemm_f16<0><<<gF, 256, SMEM_TOTAL>>>(qh, FDIM, wh + O_WOUT, b_out,
        (float*)d_out, nullptr, nullptr, ODIM, FDIM, nullptr, nullptr, nullptr, nullptr);
}